// round 2
// baseline (speedup 1.0000x reference)
#include <cuda_runtime.h>
#include <math.h>

#define HIDN 1024
#define MROWS 4096
#define SEQ 1024
#define NHEAD 16
#define HDIM 64
#define MSZ (MROWS * HIDN)

// ---------------- scratch (device globals; no allocation allowed) ----------
__device__ float g_Xn[3 * MSZ];   // LN outputs of q,k,v
__device__ float g_P [3 * MSZ];   // Q,K,V projections (rope applied in-place on Q,K)
__device__ float g_X [MSZ];       // attention output
__device__ float g_Fx[MSZ];       // LN2 output (needed twice)
__device__ float g_Fo[MSZ];       // relu(ffn) output

__device__ __forceinline__ float* slot_ptr(int s) {
  if (s < 3)  return g_Xn + (long)s * MSZ;
  if (s < 6)  return g_P  + (long)(s - 3) * MSZ;
  if (s == 6) return g_X;
  if (s == 7) return g_Fx;
  return g_Fo;
}

// ---------------- reductions ----------------
__device__ __forceinline__ float warpSum(float v) {
#pragma unroll
  for (int o = 16; o; o >>= 1) v += __shfl_xor_sync(0xffffffffu, v, o);
  return v;
}

// block of 256 threads (8 warps); safe for repeated use (leading sync)
__device__ __forceinline__ float blockSum(float partial, float* sh) {
  __syncthreads();
  float w = warpSum(partial);
  if ((threadIdx.x & 31) == 0) sh[threadIdx.x >> 5] = w;
  __syncthreads();
  float tot = 0.f;
#pragma unroll
  for (int i = 0; i < 8; i++) tot += sh[i];
  return tot;
}

__device__ __forceinline__ float red16max(float v) {
#pragma unroll
  for (int o = 8; o; o >>= 1) v = fmaxf(v, __shfl_xor_sync(0xffffffffu, v, o));
  return v;
}
__device__ __forceinline__ float red16sum(float v) {
#pragma unroll
  for (int o = 8; o; o >>= 1) v += __shfl_xor_sync(0xffffffffu, v, o);
  return v;
}

// ---------------- LayerNorm: one row per block, 256 threads ----------------
__global__ __launch_bounds__(256)
void ln_kernel(const float* __restrict__ xext, int xslot,
               const float* __restrict__ g, const float* __restrict__ b,
               int dslot) {
  __shared__ float sh[8];
  const float* x = xext ? xext : slot_ptr(xslot);
  float* y = slot_ptr(dslot);
  const int row = blockIdx.x, t = threadIdx.x;
  float4 v = ((const float4*)(x + (long)row * HIDN))[t];
  float mean = blockSum(v.x + v.y + v.z + v.w, sh) * (1.f / HIDN);
  float dx = v.x - mean, dy = v.y - mean, dz = v.z - mean, dw = v.w - mean;
  float var = blockSum(dx * dx + dy * dy + dz * dz + dw * dw, sh) * (1.f / HIDN);
  float rstd = rsqrtf(var + 1e-5f);
  float4 gv = ((const float4*)g)[t];
  float4 bv = ((const float4*)b)[t];
  float4 o = make_float4(dx * rstd * gv.x + bv.x, dy * rstd * gv.y + bv.y,
                         dz * rstd * gv.z + bv.z, dw * rstd * gv.w + bv.w);
  ((float4*)(y + (long)row * HIDN))[t] = o;
}

// out = g_Fx + LN(g_Fo)*g3 + b3
__global__ __launch_bounds__(256)
void ln_add_kernel(const float* __restrict__ g, const float* __restrict__ b,
                   float* __restrict__ out) {
  __shared__ float sh[8];
  const int row = blockIdx.x, t = threadIdx.x;
  float4 v = ((const float4*)(g_Fo + (long)row * HIDN))[t];
  float mean = blockSum(v.x + v.y + v.z + v.w, sh) * (1.f / HIDN);
  float dx = v.x - mean, dy = v.y - mean, dz = v.z - mean, dw = v.w - mean;
  float var = blockSum(dx * dx + dy * dy + dz * dz + dw * dw, sh) * (1.f / HIDN);
  float rstd = rsqrtf(var + 1e-5f);
  float4 gv = ((const float4*)g)[t];
  float4 bv = ((const float4*)b)[t];
  float4 fx = ((const float4*)(g_Fx + (long)row * HIDN))[t];
  float4 o = make_float4(fx.x + dx * rstd * gv.x + bv.x,
                         fx.y + dy * rstd * gv.y + bv.y,
                         fx.z + dz * rstd * gv.z + bv.z,
                         fx.w + dw * rstd * gv.w + bv.w);
  ((float4*)(out + (long)row * HIDN))[t] = o;
}

// ---------------- GEMM: C[M,N] = A[M,K] * W[N,K]^T + bias  (NT, K=1024) -----
// 128x128x8 tile, 256 threads, 8x8 microtile, register prefetch.
template<bool RELU>
__global__ __launch_bounds__(256, 2)
void gemm_kernel(int aslot, const float* __restrict__ W,
                 const float* __restrict__ bias, int cslot) {
  __shared__ __align__(16) float As[8][128];
  __shared__ __align__(16) float Bs[8][128];
  const float* A = slot_ptr(aslot);
  float* C = slot_ptr(cslot);
  const int t = threadIdx.x;
  const int tx4 = (t & 15) * 4, ty4 = (t >> 4) * 4;
  const int row0 = blockIdx.y * 128, col0 = blockIdx.x * 128;
  const int lr = t >> 1, lc = (t & 1) * 4;
  const float* Ap = A + (long)(row0 + lr) * HIDN + lc;
  const float* Wp = W + (long)(col0 + lr) * HIDN + lc;

  float acc[8][8];
#pragma unroll
  for (int i = 0; i < 8; i++)
#pragma unroll
    for (int j = 0; j < 8; j++) acc[i][j] = 0.f;

  float4 av = *(const float4*)Ap;
  float4 bv = *(const float4*)Wp;

  for (int k0 = 0; k0 < HIDN; k0 += 8) {
    As[lc + 0][lr] = av.x; As[lc + 1][lr] = av.y;
    As[lc + 2][lr] = av.z; As[lc + 3][lr] = av.w;
    Bs[lc + 0][lr] = bv.x; Bs[lc + 1][lr] = bv.y;
    Bs[lc + 2][lr] = bv.z; Bs[lc + 3][lr] = bv.w;
    __syncthreads();
    if (k0 + 8 < HIDN) {  // prefetch next k-tile while computing
      av = *(const float4*)(Ap + k0 + 8);
      bv = *(const float4*)(Wp + k0 + 8);
    }
#pragma unroll
    for (int kk = 0; kk < 8; kk++) {
      float4 aA = *(const float4*)&As[kk][ty4];
      float4 aB = *(const float4*)&As[kk][ty4 + 64];
      float4 bA = *(const float4*)&Bs[kk][tx4];
      float4 bB = *(const float4*)&Bs[kk][tx4 + 64];
      float a[8] = {aA.x, aA.y, aA.z, aA.w, aB.x, aB.y, aB.z, aB.w};
      float c[8] = {bA.x, bA.y, bA.z, bA.w, bB.x, bB.y, bB.z, bB.w};
#pragma unroll
      for (int i = 0; i < 8; i++)
#pragma unroll
        for (int j = 0; j < 8; j++) acc[i][j] += a[i] * c[j];
    }
    __syncthreads();
  }

  float4 bi0 = *(const float4*)&bias[col0 + tx4];
  float4 bi1 = *(const float4*)&bias[col0 + tx4 + 64];
#pragma unroll
  for (int half = 0; half < 2; half++) {
#pragma unroll
    for (int i = 0; i < 4; i++) {
      const int ii = half * 4 + i;
      const long r = row0 + half * 64 + ty4 + i;
      float4 o0 = make_float4(acc[ii][0] + bi0.x, acc[ii][1] + bi0.y,
                              acc[ii][2] + bi0.z, acc[ii][3] + bi0.w);
      float4 o1 = make_float4(acc[ii][4] + bi1.x, acc[ii][5] + bi1.y,
                              acc[ii][6] + bi1.z, acc[ii][7] + bi1.w);
      if (RELU) {
        o0.x = fmaxf(o0.x, 0.f); o0.y = fmaxf(o0.y, 0.f);
        o0.z = fmaxf(o0.z, 0.f); o0.w = fmaxf(o0.w, 0.f);
        o1.x = fmaxf(o1.x, 0.f); o1.y = fmaxf(o1.y, 0.f);
        o1.z = fmaxf(o1.z, 0.f); o1.w = fmaxf(o1.w, 0.f);
      }
      *(float4*)(C + r * HIDN + col0 + tx4) = o0;
      *(float4*)(C + r * HIDN + col0 + tx4 + 64) = o1;
    }
  }
}

// ---------------- RoPE (in-place on g_P slots 0,1) --------------------------
__global__ __launch_bounds__(512)
void rope_kernel() {
  const int row = blockIdx.x;
  float* X = blockIdx.y ? (g_P + MSZ) : g_P;
  const int t = threadIdx.x;
  const int h = t >> 5, i = t & 31;
  const int s = row & (SEQ - 1);
  // inv_freq = 10000^(-i/32) = 2^(-i*log2(10000)/32)
  float inv = exp2f(-(float)i * (13.287712379549449f / 32.f));
  float ang = (float)s * inv;
  float sn, cs;
  sincosf(ang, &sn, &cs);   // accurate: args up to ~1023 rad
  float* p = X + (long)row * HIDN + h * HDIM + i;
  float x1 = p[0], x2 = p[32];
  p[0]  = x1 * cs - x2 * sn;
  p[32] = x2 * cs + x1 * sn;
}

// ---------------- attention: one (b, h, 64-query tile) per block ------------
// 256 threads; thread (ty,tx) owns S/O 4x4 microtile rows ty*4+i, cols tx*4+j.
// KP holds K^T (conflict-free float4 reads), then reused for P.
__global__ __launch_bounds__(256)
void attn_kernel(const int* __restrict__ mask) {
  __shared__ __align__(16) float Qs[64][64];
  __shared__ __align__(16) float KP[64][64];
  __shared__ __align__(16) float Vs[64][64];
  const float* Q = g_P;
  const float* K = g_P + MSZ;
  const float* V = g_P + 2 * MSZ;
  const int t = threadIdx.x;
  const int tx = t & 15, ty = t >> 4;
  const int tx4 = tx * 4, ty4 = ty * 4;
  const int b = blockIdx.z, h = blockIdx.y, q0 = blockIdx.x * 64;

  {  // load Q tile, pre-scaled by 1/sqrt(64)
    const int r = t >> 2, c = (t & 3) * 16;
    const float* src = Q + (long)(b * SEQ + q0 + r) * HIDN + h * HDIM + c;
#pragma unroll
    for (int i = 0; i < 4; i++) {
      float4 v = *(const float4*)(src + 4 * i);
      v.x *= 0.125f; v.y *= 0.125f; v.z *= 0.125f; v.w *= 0.125f;
      *(float4*)&Qs[r][c + 4 * i] = v;
    }
  }

  float O[4][4];
#pragma unroll
  for (int i = 0; i < 4; i++)
#pragma unroll
    for (int j = 0; j < 4; j++) O[i][j] = 0.f;
  float m_run[4] = {-1e30f, -1e30f, -1e30f, -1e30f};
  float l_run[4] = {0.f, 0.f, 0.f, 0.f};

  for (int kb = 0; kb < SEQ / 64; kb++) {
    const int k0 = kb * 64;
    __syncthreads();  // prior-iter smem reads done (also covers Qs on iter 0)
    {  // load K transposed + V
      const int r = t >> 2, c = (t & 3) * 16;
      const float* ks = K + (long)(b * SEQ + k0 + r) * HIDN + h * HDIM + c;
      const float* vs = V + (long)(b * SEQ + k0 + r) * HIDN + h * HDIM + c;
#pragma unroll
      for (int i = 0; i < 4; i++) {
        float4 kv = *(const float4*)(ks + 4 * i);
        KP[c + 4 * i + 0][r] = kv.x;
        KP[c + 4 * i + 1][r] = kv.y;
        KP[c + 4 * i + 2][r] = kv.z;
        KP[c + 4 * i + 3][r] = kv.w;
        *(float4*)&Vs[r][c + 4 * i] = *(const float4*)(vs + 4 * i);
      }
    }
    const int4 mk = *(const int4*)(mask + b * SEQ + k0 + tx4);
    __syncthreads();

    float s[4][4];
#pragma unroll
    for (int i = 0; i < 4; i++)
#pragma unroll
      for (int j = 0; j < 4; j++) s[i][j] = 0.f;

#pragma unroll 8
    for (int k = 0; k < 64; k++) {
      float4 kv = *(const float4*)&KP[k][tx4];
      float qa = Qs[ty4 + 0][k], qb = Qs[ty4 + 1][k];
      float qc = Qs[ty4 + 2][k], qd = Qs[ty4 + 3][k];
      s[0][0] += qa * kv.x; s[0][1] += qa * kv.y; s[0][2] += qa * kv.z; s[0][3] += qa * kv.w;
      s[1][0] += qb * kv.x; s[1][1] += qb * kv.y; s[1][2] += qb * kv.z; s[1][3] += qb * kv.w;
      s[2][0] += qc * kv.x; s[2][1] += qc * kv.y; s[2][2] += qc * kv.z; s[2][3] += qc * kv.w;
      s[3][0] += qd * kv.x; s[3][1] += qd * kv.y; s[3][2] += qd * kv.z; s[3][3] += qd * kv.w;
    }
    // reference: scores = where(mask==0, 1e-10, scores)  (after /sqrt(hd))
#pragma unroll
    for (int i = 0; i < 4; i++) {
      if (mk.x == 0) s[i][0] = 1e-10f;
      if (mk.y == 0) s[i][1] = 1e-10f;
      if (mk.z == 0) s[i][2] = 1e-10f;
      if (mk.w == 0) s[i][3] = 1e-10f;
    }
    __syncthreads();  // all S-phase KP reads done before overwriting with P

#pragma unroll
    for (int i = 0; i < 4; i++) {
      float mb = fmaxf(fmaxf(s[i][0], s[i][1]), fmaxf(s[i][2], s[i][3]));
      mb = red16max(mb);
      float mn = fmaxf(m_run[i], mb);
      float corr = __expf(m_run[i] - mn);
      m_run[i] = mn;
      float p0 = __expf(s[i][0] - mn), p1 = __expf(s[i][1] - mn);
      float p2 = __expf(s[i][2] - mn), p3 = __expf(s[i][3] - mn);
      float ls = red16sum(p0 + p1 + p2 + p3);
      l_run[i] = l_run[i] * corr + ls;
      O[i][0] *= corr; O[i][1] *= corr; O[i][2] *= corr; O[i][3] *= corr;
      KP[ty4 + i][tx4 + 0] = p0;
      KP[ty4 + i][tx4 + 1] = p1;
      KP[ty4 + i][tx4 + 2] = p2;
      KP[ty4 + i][tx4 + 3] = p3;
    }
    __syncthreads();  // P visible to all

#pragma unroll 8
    for (int k = 0; k < 64; k++) {
      float4 vv = *(const float4*)&Vs[k][tx4];
      float pa = KP[ty4 + 0][k], pb = KP[ty4 + 1][k];
      float pc = KP[ty4 + 2][k], pd = KP[ty4 + 3][k];
      O[0][0] += pa * vv.x; O[0][1] += pa * vv.y; O[0][2] += pa * vv.z; O[0][3] += pa * vv.w;
      O[1][0] += pb * vv.x; O[1][1] += pb * vv.y; O[1][2] += pb * vv.z; O[1][3] += pb * vv.w;
      O[2][0] += pc * vv.x; O[2][1] += pc * vv.y; O[2][2] += pc * vv.z; O[2][3] += pc * vv.w;
      O[3][0] += pd * vv.x; O[3][1] += pd * vv.y; O[3][2] += pd * vv.z; O[3][3] += pd * vv.w;
    }
  }

#pragma unroll
  for (int i = 0; i < 4; i++) {
    float inv = 1.f / l_run[i];
    float4 o = make_float4(O[i][0] * inv, O[i][1] * inv,
                           O[i][2] * inv, O[i][3] * inv);
    *(float4*)(g_X + (long)(b * SEQ + q0 + ty4 + i) * HIDN + h * HDIM + tx4) = o;
  }
}

// ---------------- launch -----------------------------------------------------
extern "C" void kernel_launch(void* const* d_in, const int* in_sizes, int n_in,
                              void* d_out, int out_size) {
  const float* q   = (const float*)d_in[0];
  const float* k   = (const float*)d_in[1];
  const float* v   = (const float*)d_in[2];
  const float* g1q = (const float*)d_in[3];
  const float* b1q = (const float*)d_in[4];
  const float* g1k = (const float*)d_in[5];
  const float* b1k = (const float*)d_in[6];
  const float* g1v = (const float*)d_in[7];
  const float* b1v = (const float*)d_in[8];
  const float* Wq  = (const float*)d_in[9];
  const float* bq  = (const float*)d_in[10];
  const float* Wk  = (const float*)d_in[11];
  const float* bk  = (const float*)d_in[12];
  const float* Wv  = (const float*)d_in[13];
  const float* bv  = (const float*)d_in[14];
  const float* g2  = (const float*)d_in[15];
  const float* b2  = (const float*)d_in[16];
  const float* g3  = (const float*)d_in[17];
  const float* b3  = (const float*)d_in[18];
  const float* Wf  = (const float*)d_in[19];
  const float* bf  = (const float*)d_in[20];
  const int*  mask = (const int*)d_in[21];
  float* out = (float*)d_out;

  // 1) LayerNorms of q,k,v
  ln_kernel<<<MROWS, 256>>>(q, -1, g1q, b1q, 0);
  ln_kernel<<<MROWS, 256>>>(k, -1, g1k, b1k, 1);
  ln_kernel<<<MROWS, 256>>>(v, -1, g1v, b1v, 2);

  // 2) Q/K/V projections
  dim3 ggrid(HIDN / 128, MROWS / 128);
  gemm_kernel<false><<<ggrid, 256>>>(0, Wq, bq, 3);
  gemm_kernel<false><<<ggrid, 256>>>(1, Wk, bk, 4);
  gemm_kernel<false><<<ggrid, 256>>>(2, Wv, bv, 5);

  // 3) RoPE in-place on Q,K
  rope_kernel<<<dim3(MROWS, 2), 512>>>();

  // 4) masked flash attention
  attn_kernel<<<dim3(SEQ / 64, NHEAD, 4), 256>>>(mask);

  // 5) fx = LN(x)
  ln_kernel<<<MROWS, 256>>>(nullptr, 6, g2, b2, 7);

  // 6) fo = relu(fx @ Wf^T + bf)
  gemm_kernel<true><<<ggrid, 256>>>(7, Wf, bf, 8);

  // 7) out = fx + LN(fo)
  ln_add_kernel<<<MROWS, 256>>>(g3, b3, out);
}

// round 4
// speedup vs baseline: 1.2577x; 1.2577x over previous
#include <cuda_runtime.h>
#include <cuda_bf16.h>
#include <math.h>
#include <stdint.h>

#define HIDN 1024
#define MROWS 4096
#define SEQ 1024
#define NHEAD 16
#define HDIM 64
#define MSZ (MROWS * HIDN)
#define WSZ (HIDN * HIDN)

// mma.sync GEMM tiling
#define BM 128
#define BN 128
#define BK 32
#define LDT 40                         // row stride in bf16 elems (32 + 8 pad)
#define TBYTES (128 * LDT * 2)         // 10240 bytes per tensor tile
#define OFF_AHI 0
#define OFF_ALO (1 * TBYTES)
#define OFF_BHI (2 * TBYTES)
#define OFF_BLO (3 * TBYTES)
#define SSTRIDE (4 * TBYTES)           // 40960 per stage
#define GEMM_SMEM (3 * SSTRIDE)        // 122880, 3-stage pipeline

// ---------------- scratch (device globals; no allocation allowed) ----------
__device__ __align__(16) __nv_bfloat16 g_hi[4L * MSZ];   // bf16-hi LN outputs (0=q,1=k,2=v,3=Fx)
__device__ __align__(16) __nv_bfloat16 g_lo[4L * MSZ];   // bf16-lo residuals
__device__ __align__(16) __nv_bfloat16 g_Whi[4L * WSZ];  // weights hi (0=Wq,1=Wk,2=Wv,3=Wf)
__device__ __align__(16) __nv_bfloat16 g_Wlo[4L * WSZ];  // weights lo
__device__ __align__(16) float g_P [3L * MSZ];  // Q,K,V projections (rope in-place)
__device__ __align__(16) float g_X [MSZ];       // attention output
__device__ __align__(16) float g_Fx[MSZ];       // LN2 output (residual)
__device__ __align__(16) float g_Fo[MSZ];       // relu(ffn)

// ---------------- PTX helpers ----------------
__device__ __forceinline__ void cp16(uint32_t dst, const void* src) {
  asm volatile("cp.async.cg.shared.global [%0], [%1], 16;\n"
               :: "r"(dst), "l"(__cvta_generic_to_global(src)) : "memory");
}
#define CP_COMMIT() asm volatile("cp.async.commit_group;" ::: "memory")
#define CP_WAIT1()  asm volatile("cp.async.wait_group 1;" ::: "memory")

#define LDSM4(r, addr) asm volatile( \
  "ldmatrix.sync.aligned.m8n8.x4.shared.b16 {%0,%1,%2,%3}, [%4];" \
  : "=r"((r)[0]), "=r"((r)[1]), "=r"((r)[2]), "=r"((r)[3]) : "r"(addr))

#define MMA(acc, a, b0, b1) asm volatile( \
  "mma.sync.aligned.m16n8k16.row.col.f32.bf16.bf16.f32 " \
  "{%0,%1,%2,%3}, {%4,%5,%6,%7}, {%8,%9}, {%0,%1,%2,%3};" \
  : "+f"((acc)[0]), "+f"((acc)[1]), "+f"((acc)[2]), "+f"((acc)[3]) \
  : "r"((a)[0]), "r"((a)[1]), "r"((a)[2]), "r"((a)[3]), "r"(b0), "r"(b1))

// ---------------- reductions ----------------
__device__ __forceinline__ float warpSum(float v) {
#pragma unroll
  for (int o = 16; o; o >>= 1) v += __shfl_xor_sync(0xffffffffu, v, o);
  return v;
}
__device__ __forceinline__ float blockSum(float partial, float* sh) {
  __syncthreads();
  float w = warpSum(partial);
  if ((threadIdx.x & 31) == 0) sh[threadIdx.x >> 5] = w;
  __syncthreads();
  float tot = 0.f;
#pragma unroll
  for (int i = 0; i < 8; i++) tot += sh[i];
  return tot;
}
__device__ __forceinline__ float red16max(float v) {
#pragma unroll
  for (int o = 8; o; o >>= 1) v = fmaxf(v, __shfl_xor_sync(0xffffffffu, v, o));
  return v;
}
__device__ __forceinline__ float red16sum(float v) {
#pragma unroll
  for (int o = 8; o; o >>= 1) v += __shfl_xor_sync(0xffffffffu, v, o);
  return v;
}

// ---------------- weight split: fp32 -> bf16 hi/lo -------------------------
__global__ __launch_bounds__(256)
void wconv_kernel(const float* __restrict__ w0, const float* __restrict__ w1,
                  const float* __restrict__ w2, const float* __restrict__ w3) {
  const float* src = blockIdx.y == 0 ? w0 : blockIdx.y == 1 ? w1
                   : blockIdx.y == 2 ? w2 : w3;
  const long base = (long)blockIdx.y * WSZ;
  const long i = ((long)blockIdx.x * 256 + threadIdx.x) * 4;
  float4 v = *(const float4*)(src + i);
  __nv_bfloat16 hx = __float2bfloat16_rn(v.x), hy = __float2bfloat16_rn(v.y);
  __nv_bfloat16 hz = __float2bfloat16_rn(v.z), hw = __float2bfloat16_rn(v.w);
  __nv_bfloat16 lx = __float2bfloat16_rn(v.x - __bfloat162float(hx));
  __nv_bfloat16 ly = __float2bfloat16_rn(v.y - __bfloat162float(hy));
  __nv_bfloat16 lz = __float2bfloat16_rn(v.z - __bfloat162float(hz));
  __nv_bfloat16 lw = __float2bfloat16_rn(v.w - __bfloat162float(hw));
  *(__nv_bfloat162*)(g_Whi + base + i)     = __nv_bfloat162(hx, hy);
  *(__nv_bfloat162*)(g_Whi + base + i + 2) = __nv_bfloat162(hz, hw);
  *(__nv_bfloat162*)(g_Wlo + base + i)     = __nv_bfloat162(lx, ly);
  *(__nv_bfloat162*)(g_Wlo + base + i + 2) = __nv_bfloat162(lz, lw);
}

// ---------------- LayerNorm -> bf16 hi/lo (optionally fp32 g_Fx) -----------
__global__ __launch_bounds__(256)
void ln_bf16_kernel(const float* __restrict__ xext, const float* __restrict__ g,
                    const float* __restrict__ b, int slot, int writeFx) {
  __shared__ float sh[8];
  const float* x = xext ? xext : g_X;
  const int row = blockIdx.x, t = threadIdx.x;
  float4 v = ((const float4*)(x + (long)row * HIDN))[t];
  float mean = blockSum(v.x + v.y + v.z + v.w, sh) * (1.f / HIDN);
  float dx = v.x - mean, dy = v.y - mean, dz = v.z - mean, dw = v.w - mean;
  float var = blockSum(dx * dx + dy * dy + dz * dz + dw * dw, sh) * (1.f / HIDN);
  float rstd = rsqrtf(var + 1e-5f);
  float4 gv = ((const float4*)g)[t];
  float4 bv = ((const float4*)b)[t];
  float4 o = make_float4(dx * rstd * gv.x + bv.x, dy * rstd * gv.y + bv.y,
                         dz * rstd * gv.z + bv.z, dw * rstd * gv.w + bv.w);
  if (writeFx) ((float4*)(g_Fx + (long)row * HIDN))[t] = o;
  const long off = (long)slot * MSZ + (long)row * HIDN + t * 4;
  __nv_bfloat16 hx = __float2bfloat16_rn(o.x), hy = __float2bfloat16_rn(o.y);
  __nv_bfloat16 hz = __float2bfloat16_rn(o.z), hw = __float2bfloat16_rn(o.w);
  __nv_bfloat16 lx = __float2bfloat16_rn(o.x - __bfloat162float(hx));
  __nv_bfloat16 ly = __float2bfloat16_rn(o.y - __bfloat162float(hy));
  __nv_bfloat16 lz = __float2bfloat16_rn(o.z - __bfloat162float(hz));
  __nv_bfloat16 lw = __float2bfloat16_rn(o.w - __bfloat162float(hw));
  *(__nv_bfloat162*)(g_hi + off)     = __nv_bfloat162(hx, hy);
  *(__nv_bfloat162*)(g_hi + off + 2) = __nv_bfloat162(hz, hw);
  *(__nv_bfloat162*)(g_lo + off)     = __nv_bfloat162(lx, ly);
  *(__nv_bfloat162*)(g_lo + off + 2) = __nv_bfloat162(lz, lw);
}

// out = g_Fx + LN(g_Fo)*g3 + b3
__global__ __launch_bounds__(256)
void ln_add_kernel(const float* __restrict__ g, const float* __restrict__ b,
                   float* __restrict__ out) {
  __shared__ float sh[8];
  const int row = blockIdx.x, t = threadIdx.x;
  float4 v = ((const float4*)(g_Fo + (long)row * HIDN))[t];
  float mean = blockSum(v.x + v.y + v.z + v.w, sh) * (1.f / HIDN);
  float dx = v.x - mean, dy = v.y - mean, dz = v.z - mean, dw = v.w - mean;
  float var = blockSum(dx * dx + dy * dy + dz * dz + dw * dw, sh) * (1.f / HIDN);
  float rstd = rsqrtf(var + 1e-5f);
  float4 gv = ((const float4*)g)[t];
  float4 bv = ((const float4*)b)[t];
  float4 fx = ((const float4*)(g_Fx + (long)row * HIDN))[t];
  float4 o = make_float4(fx.x + dx * rstd * gv.x + bv.x,
                         fx.y + dy * rstd * gv.y + bv.y,
                         fx.z + dz * rstd * gv.z + bv.z,
                         fx.w + dw * rstd * gv.w + bv.w);
  ((float4*)(out + (long)row * HIDN))[t] = o;
}

// ---------------- split-bf16 mma.sync GEMM: C = A @ W^T + bias -------------
// Block 128x128, 8 warps (2x4), warp tile 64x32, K staged 32, 3-stage cp.async.
__device__ __forceinline__ void gemm_load_stage(
    uint32_t sbase, const __nv_bfloat16* Ah, const __nv_bfloat16* Al,
    const __nv_bfloat16* Bh, const __nv_bfloat16* Bl,
    int row0, int col0, int k0, int t) {
#pragma unroll
  for (int j = 0; j < 2; j++) {
    const int idx = t + j * 256;
    const int r = idx >> 2, cc = idx & 3;
    const uint32_t so = sbase + (uint32_t)(r * (LDT * 2) + cc * 16);
    const long ga = (long)(row0 + r) * HIDN + k0 + cc * 8;
    const long gb = (long)(col0 + r) * HIDN + k0 + cc * 8;
    cp16(so + OFF_AHI, Ah + ga);
    cp16(so + OFF_ALO, Al + ga);
    cp16(so + OFF_BHI, Bh + gb);
    cp16(so + OFF_BLO, Bl + gb);
  }
}

__global__ __launch_bounds__(256, 1)
void gemm_mma(int aslot0, int cdst, int relu,
              const float* __restrict__ bias0, const float* __restrict__ bias1,
              const float* __restrict__ bias2) {
  extern __shared__ __align__(128) char smem[];
  const int z = blockIdx.z;
  const int slot = aslot0 + z;
  const __nv_bfloat16* Ah = g_hi  + (long)slot * MSZ;
  const __nv_bfloat16* Al = g_lo  + (long)slot * MSZ;
  const __nv_bfloat16* Bh = g_Whi + (long)slot * WSZ;
  const __nv_bfloat16* Bl = g_Wlo + (long)slot * WSZ;
  float* C = cdst ? g_Fo : (g_P + (long)z * MSZ);
  const float* bias = (z == 0) ? bias0 : ((z == 1) ? bias1 : bias2);

  const int t = threadIdx.x;
  const int wid = t >> 5, lane = t & 31;
  const int wm = wid >> 2, wn = wid & 3;
  const int row0 = blockIdx.y * BM, col0 = blockIdx.x * BN;
  const uint32_t sb = (uint32_t)__cvta_generic_to_shared(smem);

  float acc[4][4][4];
#pragma unroll
  for (int i = 0; i < 4; i++)
#pragma unroll
    for (int j = 0; j < 4; j++)
#pragma unroll
      for (int r = 0; r < 4; r++) acc[i][j][r] = 0.f;

  // prologue: stages 0, 1
  gemm_load_stage(sb,           Ah, Al, Bh, Bl, row0, col0, 0,  t);
  CP_COMMIT();
  gemm_load_stage(sb + SSTRIDE, Ah, Al, Bh, Bl, row0, col0, BK, t);
  CP_COMMIT();

  // per-thread ldmatrix base offsets (bytes)
  const uint32_t aOff = (uint32_t)((wm * 64 + (lane & 15)) * (LDT * 2) + (lane >> 4) * 16);
  const uint32_t bOff = (uint32_t)((wn * 32 + (lane & 15)) * (LDT * 2) + (lane >> 4) * 16);

  for (int s = 0; s < HIDN / BK; s++) {
    CP_WAIT1();
    __syncthreads();
    const uint32_t st = sb + (uint32_t)((s % 3) * SSTRIDE);
#pragma unroll
    for (int kk = 0; kk < 2; kk++) {
      uint32_t ah[4][4], al[4][4];
#pragma unroll
      for (int mi = 0; mi < 4; mi++) {
        const uint32_t a = st + aOff + (uint32_t)(mi * 16 * (LDT * 2) + kk * 32);
        LDSM4(ah[mi], a + OFF_AHI);
        LDSM4(al[mi], a + OFF_ALO);
      }
      uint32_t bh[2][4], bl[2][4];
#pragma unroll
      for (int bn = 0; bn < 2; bn++) {
        const uint32_t a = st + bOff + (uint32_t)(bn * 16 * (LDT * 2) + kk * 32);
        LDSM4(bh[bn], a + OFF_BHI);
        LDSM4(bl[bn], a + OFF_BLO);
      }
#pragma unroll
      for (int mi = 0; mi < 4; mi++) {
#pragma unroll
        for (int bn = 0; bn < 2; bn++) {
          const int ni = bn * 2;
          MMA(acc[mi][ni],     ah[mi], bh[bn][0], bh[bn][2]);
          MMA(acc[mi][ni],     ah[mi], bl[bn][0], bl[bn][2]);
          MMA(acc[mi][ni],     al[mi], bh[bn][0], bh[bn][2]);
          MMA(acc[mi][ni + 1], ah[mi], bh[bn][1], bh[bn][3]);
          MMA(acc[mi][ni + 1], ah[mi], bl[bn][1], bl[bn][3]);
          MMA(acc[mi][ni + 1], al[mi], bh[bn][1], bh[bn][3]);
        }
      }
    }
    __syncthreads();
    const int sn = s + 2;
    if (sn < HIDN / BK) {
      gemm_load_stage(sb + (uint32_t)((sn % 3) * SSTRIDE), Ah, Al, Bh, Bl,
                      row0, col0, sn * BK, t);
    }
    CP_COMMIT();
  }

  // epilogue: c-fragment (m = lane/4 + {0,8}, n = (lane%4)*2 + {0,1})
#pragma unroll
  for (int mi = 0; mi < 4; mi++) {
    const long r = row0 + wm * 64 + mi * 16 + (lane >> 2);
#pragma unroll
    for (int ni = 0; ni < 4; ni++) {
      const int c = col0 + wn * 32 + ni * 8 + (lane & 3) * 2;
      float2 bv = *(const float2*)(bias + c);
      float v0 = acc[mi][ni][0] + bv.x, v1 = acc[mi][ni][1] + bv.y;
      float v2 = acc[mi][ni][2] + bv.x, v3 = acc[mi][ni][3] + bv.y;
      if (relu) {
        v0 = fmaxf(v0, 0.f); v1 = fmaxf(v1, 0.f);
        v2 = fmaxf(v2, 0.f); v3 = fmaxf(v3, 0.f);
      }
      *(float2*)(C + r * HIDN + c)       = make_float2(v0, v1);
      *(float2*)(C + (r + 8) * HIDN + c) = make_float2(v2, v3);
    }
  }
}

// ---------------- RoPE (in-place on g_P slots 0,1) --------------------------
__global__ __launch_bounds__(512)
void rope_kernel() {
  const int row = blockIdx.x;
  float* X = blockIdx.y ? (g_P + MSZ) : g_P;
  const int t = threadIdx.x;
  const int h = t >> 5, i = t & 31;
  const int s = row & (SEQ - 1);
  float inv = exp2f(-(float)i * (13.287712379549449f / 32.f));
  float ang = (float)s * inv;
  float sn, cs;
  sincosf(ang, &sn, &cs);
  float* p = X + (long)row * HIDN + h * HDIM + i;
  float x1 = p[0], x2 = p[32];
  p[0]  = x1 * cs - x2 * sn;
  p[32] = x2 * cs + x1 * sn;
}

// ---------------- attention: one (b, h, 64-query tile) per block ------------
__global__ __launch_bounds__(256)
void attn_kernel(const int* __restrict__ mask) {
  __shared__ __align__(16) float Qs[64][64];
  __shared__ __align__(16) float KP[64][64];
  __shared__ __align__(16) float Vs[64][64];
  const float* Q = g_P;
  const float* K = g_P + MSZ;
  const float* V = g_P + 2 * MSZ;
  const int t = threadIdx.x;
  const int tx = t & 15, ty = t >> 4;
  const int tx4 = tx * 4, ty4 = ty * 4;
  const int b = blockIdx.z, h = blockIdx.y, q0 = blockIdx.x * 64;

  {
    const int r = t >> 2, c = (t & 3) * 16;
    const float* src = Q + (long)(b * SEQ + q0 + r) * HIDN + h * HDIM + c;
#pragma unroll
    for (int i = 0; i < 4; i++) {
      float4 v = *(const float4*)(src + 4 * i);
      v.x *= 0.125f; v.y *= 0.125f; v.z *= 0.125f; v.w *= 0.125f;
      *(float4*)&Qs[r][c + 4 * i] = v;
    }
  }

  float O[4][4];
#pragma unroll
  for (int i = 0; i < 4; i++)
#pragma unroll
    for (int j = 0; j < 4; j++) O[i][j] = 0.f;
  float m_run[4] = {-1e30f, -1e30f, -1e30f, -1e30f};
  float l_run[4] = {0.f, 0.f, 0.f, 0.f};

  for (int kb = 0; kb < SEQ / 64; kb++) {
    const int k0 = kb * 64;
    __syncthreads();
    {
      const int r = t >> 2, c = (t & 3) * 16;
      const float* ks = K + (long)(b * SEQ + k0 + r) * HIDN + h * HDIM + c;
      const float* vs = V + (long)(b * SEQ + k0 + r) * HIDN + h * HDIM + c;
#pragma unroll
      for (int i = 0; i < 4; i++) {
        float4 kv = *(const float4*)(ks + 4 * i);
        KP[c + 4 * i + 0][r] = kv.x;
        KP[c + 4 * i + 1][r] = kv.y;
        KP[c + 4 * i + 2][r] = kv.z;
        KP[c + 4 * i + 3][r] = kv.w;
        *(float4*)&Vs[r][c + 4 * i] = *(const float4*)(vs + 4 * i);
      }
    }
    const int4 mk = *(const int4*)(mask + b * SEQ + k0 + tx4);
    __syncthreads();

    float s[4][4];
#pragma unroll
    for (int i = 0; i < 4; i++)
#pragma unroll
      for (int j = 0; j < 4; j++) s[i][j] = 0.f;

#pragma unroll 8
    for (int k = 0; k < 64; k++) {
      float4 kv = *(const float4*)&KP[k][tx4];
      float qa = Qs[ty4 + 0][k], qb = Qs[ty4 + 1][k];
      float qc = Qs[ty4 + 2][k], qd = Qs[ty4 + 3][k];
      s[0][0] += qa * kv.x; s[0][1] += qa * kv.y; s[0][2] += qa * kv.z; s[0][3] += qa * kv.w;
      s[1][0] += qb * kv.x; s[1][1] += qb * kv.y; s[1][2] += qb * kv.z; s[1][3] += qb * kv.w;
      s[2][0] += qc * kv.x; s[2][1] += qc * kv.y; s[2][2] += qc * kv.z; s[2][3] += qc * kv.w;
      s[3][0] += qd * kv.x; s[3][1] += qd * kv.y; s[3][2] += qd * kv.z; s[3][3] += qd * kv.w;
    }
#pragma unroll
    for (int i = 0; i < 4; i++) {
      if (mk.x == 0) s[i][0] = 1e-10f;
      if (mk.y == 0) s[i][1] = 1e-10f;
      if (mk.z == 0) s[i][2] = 1e-10f;
      if (mk.w == 0) s[i][3] = 1e-10f;
    }
    __syncthreads();

#pragma unroll
    for (int i = 0; i < 4; i++) {
      float mb = fmaxf(fmaxf(s[i][0], s[i][1]), fmaxf(s[i][2], s[i][3]));
      mb = red16max(mb);
      float mn = fmaxf(m_run[i], mb);
      float corr = __expf(m_run[i] - mn);
      m_run[i] = mn;
      float p0 = __expf(s[i][0] - mn), p1 = __expf(s[i][1] - mn);
      float p2 = __expf(s[i][2] - mn), p3 = __expf(s[i][3] - mn);
      float ls = red16sum(p0 + p1 + p2 + p3);
      l_run[i] = l_run[i] * corr + ls;
      O[i][0] *= corr; O[i][1] *= corr; O[i][2] *= corr; O[i][3] *= corr;
      KP[ty4 + i][tx4 + 0] = p0;
      KP[ty4 + i][tx4 + 1] = p1;
      KP[ty4 + i][tx4 + 2] = p2;
      KP[ty4 + i][tx4 + 3] = p3;
    }
    __syncthreads();

#pragma unroll 8
    for (int k = 0; k < 64; k++) {
      float4 vv = *(const float4*)&Vs[k][tx4];
      float pa = KP[ty4 + 0][k], pb = KP[ty4 + 1][k];
      float pc = KP[ty4 + 2][k], pd = KP[ty4 + 3][k];
      O[0][0] += pa * vv.x; O[0][1] += pa * vv.y; O[0][2] += pa * vv.z; O[0][3] += pa * vv.w;
      O[1][0] += pb * vv.x; O[1][1] += pb * vv.y; O[1][2] += pb * vv.z; O[1][3] += pb * vv.w;
      O[2][0] += pc * vv.x; O[2][1] += pc * vv.y; O[2][2] += pc * vv.z; O[2][3] += pc * vv.w;
      O[3][0] += pd * vv.x; O[3][1] += pd * vv.y; O[3][2] += pd * vv.z; O[3][3] += pd * vv.w;
    }
  }

#pragma unroll
  for (int i = 0; i < 4; i++) {
    float inv = 1.f / l_run[i];
    float4 o = make_float4(O[i][0] * inv, O[i][1] * inv,
                           O[i][2] * inv, O[i][3] * inv);
    *(float4*)(g_X + (long)(b * SEQ + q0 + ty4 + i) * HIDN + h * HDIM + tx4) = o;
  }
}

// ---------------- launch -----------------------------------------------------
extern "C" void kernel_launch(void* const* d_in, const int* in_sizes, int n_in,
                              void* d_out, int out_size) {
  const float* q   = (const float*)d_in[0];
  const float* k   = (const float*)d_in[1];
  const float* v   = (const float*)d_in[2];
  const float* g1q = (const float*)d_in[3];
  const float* b1q = (const float*)d_in[4];
  const float* g1k = (const float*)d_in[5];
  const float* b1k = (const float*)d_in[6];
  const float* g1v = (const float*)d_in[7];
  const float* b1v = (const float*)d_in[8];
  const float* Wq  = (const float*)d_in[9];
  const float* bq  = (const float*)d_in[10];
  const float* Wk  = (const float*)d_in[11];
  const float* bk  = (const float*)d_in[12];
  const float* Wv  = (const float*)d_in[13];
  const float* bv  = (const float*)d_in[14];
  const float* g2  = (const float*)d_in[15];
  const float* b2  = (const float*)d_in[16];
  const float* g3  = (const float*)d_in[17];
  const float* b3  = (const float*)d_in[18];
  const float* Wf  = (const float*)d_in[19];
  const float* bf  = (const float*)d_in[20];
  const int*  mask = (const int*)d_in[21];
  float* out = (float*)d_out;

  cudaFuncSetAttribute(gemm_mma, cudaFuncAttributeMaxDynamicSharedMemorySize, GEMM_SMEM);

  // 0) weight split (hi/lo bf16)
  wconv_kernel<<<dim3(WSZ / 1024, 4), 256>>>(Wq, Wk, Wv, Wf);

  // 1) LayerNorms of q,k,v -> bf16 hi/lo slots 0..2
  ln_bf16_kernel<<<MROWS, 256>>>(q, g1q, b1q, 0, 0);
  ln_bf16_kernel<<<MROWS, 256>>>(k, g1k, b1k, 1, 0);
  ln_bf16_kernel<<<MROWS, 256>>>(v, g1v, b1v, 2, 0);

  // 2) Q/K/V projections via mma.sync (fused z=0..2)
  dim3 ggrid(HIDN / BN, MROWS / BM, 3);
  gemm_mma<<<ggrid, 256, GEMM_SMEM>>>(0, 0, 0, bq, bk, bv);

  // 3) RoPE in-place on Q,K
  rope_kernel<<<dim3(MROWS, 2), 512>>>();

  // 4) masked flash attention -> g_X
  attn_kernel<<<dim3(SEQ / 64, NHEAD, 4), 256>>>(mask);

  // 5) fx = LN(x) -> g_Fx (fp32) + slot 3 (bf16 hi/lo)
  ln_bf16_kernel<<<MROWS, 256>>>(nullptr, g2, b2, 3, 1);

  // 6) fo = relu(fx @ Wf^T + bf) via mma.sync
  gemm_mma<<<dim3(HIDN / BN, MROWS / BM, 1), 256, GEMM_SMEM>>>(3, 1, 1, bf, bf, bf);

  // 7) out = fx + LN(fo)
  ln_add_kernel<<<MROWS, 256>>>(g3, b3, out);
}

// round 5
// speedup vs baseline: 1.8687x; 1.4858x over previous
#include <cuda_runtime.h>
#include <cuda_bf16.h>
#include <math.h>
#include <stdint.h>

#define HIDN 1024
#define MROWS 4096
#define SEQ 1024
#define NHEAD 16
#define HDIM 64
#define MSZ (MROWS * HIDN)
#define WSZ (HIDN * HIDN)

// mma.sync GEMM tiling
#define BM 128
#define BN 128
#define BK 32
#define LDT 40                         // row stride in bf16 elems (32 + 8 pad)
#define TBYTES (128 * LDT * 2)         // 10240 bytes per tensor tile
#define OFF_AHI 0
#define OFF_ALO (1 * TBYTES)
#define OFF_BHI (2 * TBYTES)
#define OFF_BLO (3 * TBYTES)
#define SSTRIDE (4 * TBYTES)           // 40960 per stage
#define GEMM_SMEM (3 * SSTRIDE)        // 122880, 3-stage pipeline

// attention tiling
#define ALD 72                         // 64 + 8 pad bf16 elems per row
#define ATILE_B (64 * ALD * 2)         // 9216 bytes per 64x64 bf16 tile
#define SQH 0
#define SQL (1 * ATILE_B)
#define SKH (2 * ATILE_B)
#define SKL (3 * ATILE_B)
#define SVH (4 * ATILE_B)
#define SVL (5 * ATILE_B)
#define SMSK (6 * ATILE_B)
#define ATTN_SMEM (SMSK + 256)

// ---------------- scratch (device globals; no allocation allowed) ----------
__device__ __align__(16) __nv_bfloat16 g_hi[4L * MSZ];   // hi: LN outs, then rope'd Q/K/V
__device__ __align__(16) __nv_bfloat16 g_lo[4L * MSZ];   // lo residuals
__device__ __align__(16) __nv_bfloat16 g_Whi[4L * WSZ];  // weights hi (0=Wq,1=Wk,2=Wv,3=Wf)
__device__ __align__(16) __nv_bfloat16 g_Wlo[4L * WSZ];  // weights lo
__device__ __align__(16) float g_P [3L * MSZ];  // Q,K,V projections fp32
__device__ __align__(16) float g_X [MSZ];       // attention output
__device__ __align__(16) float g_Fx[MSZ];       // LN2 output (residual)
__device__ __align__(16) float g_Fo[MSZ];       // relu(ffn)

// ---------------- PTX helpers ----------------
__device__ __forceinline__ void cp16(uint32_t dst, const void* src) {
  asm volatile("cp.async.cg.shared.global [%0], [%1], 16;\n"
               :: "r"(dst), "l"(__cvta_generic_to_global(src)) : "memory");
}
#define CP_COMMIT() asm volatile("cp.async.commit_group;" ::: "memory")
#define CP_WAIT1()  asm volatile("cp.async.wait_group 1;" ::: "memory")
#define CP_WAIT0()  asm volatile("cp.async.wait_group 0;" ::: "memory")

#define LDSM4(r, addr) asm volatile( \
  "ldmatrix.sync.aligned.m8n8.x4.shared.b16 {%0,%1,%2,%3}, [%4];" \
  : "=r"((r)[0]), "=r"((r)[1]), "=r"((r)[2]), "=r"((r)[3]) : "r"(addr))

#define LDSM4T(r, addr) asm volatile( \
  "ldmatrix.sync.aligned.m8n8.x4.trans.shared.b16 {%0,%1,%2,%3}, [%4];" \
  : "=r"((r)[0]), "=r"((r)[1]), "=r"((r)[2]), "=r"((r)[3]) : "r"(addr))

#define MMA(acc, a, b0, b1) asm volatile( \
  "mma.sync.aligned.m16n8k16.row.col.f32.bf16.bf16.f32 " \
  "{%0,%1,%2,%3}, {%4,%5,%6,%7}, {%8,%9}, {%0,%1,%2,%3};" \
  : "+f"((acc)[0]), "+f"((acc)[1]), "+f"((acc)[2]), "+f"((acc)[3]) \
  : "r"((a)[0]), "r"((a)[1]), "r"((a)[2]), "r"((a)[3]), "r"(b0), "r"(b1))

__device__ __forceinline__ uint32_t packbf2(float a, float b) {
  __nv_bfloat162 v(__float2bfloat16_rn(a), __float2bfloat16_rn(b));
  return *(uint32_t*)&v;
}
__device__ __forceinline__ void split2(float a, float b, uint32_t& hi, uint32_t& lo) {
  __nv_bfloat16 ha = __float2bfloat16_rn(a), hb = __float2bfloat16_rn(b);
  __nv_bfloat162 h(ha, hb);
  __nv_bfloat162 l(__float2bfloat16_rn(a - __bfloat162float(ha)),
                   __float2bfloat16_rn(b - __bfloat162float(hb)));
  hi = *(uint32_t*)&h;
  lo = *(uint32_t*)&l;
}

// ---------------- reductions ----------------
__device__ __forceinline__ float warpSum(float v) {
#pragma unroll
  for (int o = 16; o; o >>= 1) v += __shfl_xor_sync(0xffffffffu, v, o);
  return v;
}
__device__ __forceinline__ float blockSum(float partial, float* sh) {
  __syncthreads();
  float w = warpSum(partial);
  if ((threadIdx.x & 31) == 0) sh[threadIdx.x >> 5] = w;
  __syncthreads();
  float tot = 0.f;
#pragma unroll
  for (int i = 0; i < 8; i++) tot += sh[i];
  return tot;
}

// ---------------- weight split: fp32 -> bf16 hi/lo -------------------------
__global__ __launch_bounds__(256)
void wconv_kernel(const float* __restrict__ w0, const float* __restrict__ w1,
                  const float* __restrict__ w2, const float* __restrict__ w3) {
  const float* src = blockIdx.y == 0 ? w0 : blockIdx.y == 1 ? w1
                   : blockIdx.y == 2 ? w2 : w3;
  const long base = (long)blockIdx.y * WSZ;
  const long i = ((long)blockIdx.x * 256 + threadIdx.x) * 4;
  float4 v = *(const float4*)(src + i);
  uint32_t h0, l0, h1, l1;
  split2(v.x, v.y, h0, l0);
  split2(v.z, v.w, h1, l1);
  *(uint32_t*)(g_Whi + base + i)     = h0;
  *(uint32_t*)(g_Whi + base + i + 2) = h1;
  *(uint32_t*)(g_Wlo + base + i)     = l0;
  *(uint32_t*)(g_Wlo + base + i + 2) = l1;
}

// ---------------- LayerNorm -> bf16 hi/lo (optionally fp32 g_Fx) -----------
__global__ __launch_bounds__(256)
void ln_bf16_kernel(const float* __restrict__ xext, const float* __restrict__ g,
                    const float* __restrict__ b, int slot, int writeFx) {
  __shared__ float sh[8];
  const float* x = xext ? xext : g_X;
  const int row = blockIdx.x, t = threadIdx.x;
  float4 v = ((const float4*)(x + (long)row * HIDN))[t];
  float mean = blockSum(v.x + v.y + v.z + v.w, sh) * (1.f / HIDN);
  float dx = v.x - mean, dy = v.y - mean, dz = v.z - mean, dw = v.w - mean;
  float var = blockSum(dx * dx + dy * dy + dz * dz + dw * dw, sh) * (1.f / HIDN);
  float rstd = rsqrtf(var + 1e-5f);
  float4 gv = ((const float4*)g)[t];
  float4 bv = ((const float4*)b)[t];
  float4 o = make_float4(dx * rstd * gv.x + bv.x, dy * rstd * gv.y + bv.y,
                         dz * rstd * gv.z + bv.z, dw * rstd * gv.w + bv.w);
  if (writeFx) ((float4*)(g_Fx + (long)row * HIDN))[t] = o;
  const long off = (long)slot * MSZ + (long)row * HIDN + t * 4;
  uint32_t h0, l0, h1, l1;
  split2(o.x, o.y, h0, l0);
  split2(o.z, o.w, h1, l1);
  *(uint32_t*)(g_hi + off)     = h0;
  *(uint32_t*)(g_hi + off + 2) = h1;
  *(uint32_t*)(g_lo + off)     = l0;
  *(uint32_t*)(g_lo + off + 2) = l1;
}

// out = g_Fx + LN(g_Fo)*g3 + b3
__global__ __launch_bounds__(256)
void ln_add_kernel(const float* __restrict__ g, const float* __restrict__ b,
                   float* __restrict__ out) {
  __shared__ float sh[8];
  const int row = blockIdx.x, t = threadIdx.x;
  float4 v = ((const float4*)(g_Fo + (long)row * HIDN))[t];
  float mean = blockSum(v.x + v.y + v.z + v.w, sh) * (1.f / HIDN);
  float dx = v.x - mean, dy = v.y - mean, dz = v.z - mean, dw = v.w - mean;
  float var = blockSum(dx * dx + dy * dy + dz * dz + dw * dw, sh) * (1.f / HIDN);
  float rstd = rsqrtf(var + 1e-5f);
  float4 gv = ((const float4*)g)[t];
  float4 bv = ((const float4*)b)[t];
  float4 fx = ((const float4*)(g_Fx + (long)row * HIDN))[t];
  float4 o = make_float4(fx.x + dx * rstd * gv.x + bv.x,
                         fx.y + dy * rstd * gv.y + bv.y,
                         fx.z + dz * rstd * gv.z + bv.z,
                         fx.w + dw * rstd * gv.w + bv.w);
  ((float4*)(out + (long)row * HIDN))[t] = o;
}

// ---------------- split-bf16 mma.sync GEMM: C = A @ W^T + bias -------------
__device__ __forceinline__ void gemm_load_stage(
    uint32_t sbase, const __nv_bfloat16* Ah, const __nv_bfloat16* Al,
    const __nv_bfloat16* Bh, const __nv_bfloat16* Bl,
    int row0, int col0, int k0, int t) {
#pragma unroll
  for (int j = 0; j < 2; j++) {
    const int idx = t + j * 256;
    const int r = idx >> 2, cc = idx & 3;
    const uint32_t so = sbase + (uint32_t)(r * (LDT * 2) + cc * 16);
    const long ga = (long)(row0 + r) * HIDN + k0 + cc * 8;
    const long gb = (long)(col0 + r) * HIDN + k0 + cc * 8;
    cp16(so + OFF_AHI, Ah + ga);
    cp16(so + OFF_ALO, Al + ga);
    cp16(so + OFF_BHI, Bh + gb);
    cp16(so + OFF_BLO, Bl + gb);
  }
}

__global__ __launch_bounds__(256, 1)
void gemm_mma(int aslot0, int cdst, int relu,
              const float* __restrict__ bias0, const float* __restrict__ bias1,
              const float* __restrict__ bias2) {
  extern __shared__ __align__(128) char smem[];
  const int z = blockIdx.z;
  const int slot = aslot0 + z;
  const __nv_bfloat16* Ah = g_hi  + (long)slot * MSZ;
  const __nv_bfloat16* Al = g_lo  + (long)slot * MSZ;
  const __nv_bfloat16* Bh = g_Whi + (long)slot * WSZ;
  const __nv_bfloat16* Bl = g_Wlo + (long)slot * WSZ;
  float* C = cdst ? g_Fo : (g_P + (long)z * MSZ);
  const float* bias = (z == 0) ? bias0 : ((z == 1) ? bias1 : bias2);

  const int t = threadIdx.x;
  const int wid = t >> 5, lane = t & 31;
  const int wm = wid >> 2, wn = wid & 3;
  const int row0 = blockIdx.y * BM, col0 = blockIdx.x * BN;
  const uint32_t sb = (uint32_t)__cvta_generic_to_shared(smem);

  float acc[4][4][4];
#pragma unroll
  for (int i = 0; i < 4; i++)
#pragma unroll
    for (int j = 0; j < 4; j++)
#pragma unroll
      for (int r = 0; r < 4; r++) acc[i][j][r] = 0.f;

  gemm_load_stage(sb,           Ah, Al, Bh, Bl, row0, col0, 0,  t);
  CP_COMMIT();
  gemm_load_stage(sb + SSTRIDE, Ah, Al, Bh, Bl, row0, col0, BK, t);
  CP_COMMIT();

  const uint32_t aOff = (uint32_t)((wm * 64 + (lane & 15)) * (LDT * 2) + (lane >> 4) * 16);
  const uint32_t bOff = (uint32_t)((wn * 32 + (lane & 15)) * (LDT * 2) + (lane >> 4) * 16);

  for (int s = 0; s < HIDN / BK; s++) {
    CP_WAIT1();
    __syncthreads();
    const uint32_t st = sb + (uint32_t)((s % 3) * SSTRIDE);
#pragma unroll
    for (int kk = 0; kk < 2; kk++) {
      uint32_t ah[4][4], al[4][4];
#pragma unroll
      for (int mi = 0; mi < 4; mi++) {
        const uint32_t a = st + aOff + (uint32_t)(mi * 16 * (LDT * 2) + kk * 32);
        LDSM4(ah[mi], a + OFF_AHI);
        LDSM4(al[mi], a + OFF_ALO);
      }
      uint32_t bh[2][4], bl[2][4];
#pragma unroll
      for (int bn = 0; bn < 2; bn++) {
        const uint32_t a = st + bOff + (uint32_t)(bn * 16 * (LDT * 2) + kk * 32);
        LDSM4(bh[bn], a + OFF_BHI);
        LDSM4(bl[bn], a + OFF_BLO);
      }
#pragma unroll
      for (int mi = 0; mi < 4; mi++) {
#pragma unroll
        for (int bn = 0; bn < 2; bn++) {
          const int ni = bn * 2;
          MMA(acc[mi][ni],     ah[mi], bh[bn][0], bh[bn][2]);
          MMA(acc[mi][ni],     ah[mi], bl[bn][0], bl[bn][2]);
          MMA(acc[mi][ni],     al[mi], bh[bn][0], bh[bn][2]);
          MMA(acc[mi][ni + 1], ah[mi], bh[bn][1], bh[bn][3]);
          MMA(acc[mi][ni + 1], ah[mi], bl[bn][1], bl[bn][3]);
          MMA(acc[mi][ni + 1], al[mi], bh[bn][1], bh[bn][3]);
        }
      }
    }
    __syncthreads();
    const int sn = s + 2;
    if (sn < HIDN / BK) {
      gemm_load_stage(sb + (uint32_t)((sn % 3) * SSTRIDE), Ah, Al, Bh, Bl,
                      row0, col0, sn * BK, t);
    }
    CP_COMMIT();
  }

#pragma unroll
  for (int mi = 0; mi < 4; mi++) {
    const long r = row0 + wm * 64 + mi * 16 + (lane >> 2);
#pragma unroll
    for (int ni = 0; ni < 4; ni++) {
      const int c = col0 + wn * 32 + ni * 8 + (lane & 3) * 2;
      float2 bv = *(const float2*)(bias + c);
      float v0 = acc[mi][ni][0] + bv.x, v1 = acc[mi][ni][1] + bv.y;
      float v2 = acc[mi][ni][2] + bv.x, v3 = acc[mi][ni][3] + bv.y;
      if (relu) {
        v0 = fmaxf(v0, 0.f); v1 = fmaxf(v1, 0.f);
        v2 = fmaxf(v2, 0.f); v3 = fmaxf(v3, 0.f);
      }
      *(float2*)(C + r * HIDN + c)       = make_float2(v0, v1);
      *(float2*)(C + (r + 8) * HIDN + c) = make_float2(v2, v3);
    }
  }
}

// ---------------- RoPE + split to bf16 hi/lo slots 0,1,2 -------------------
// y=0: Q (rope), y=1: K (rope), y=2: V (plain convert)
__global__ __launch_bounds__(512)
void rope_split_kernel() {
  const int row = blockIdx.x, y = blockIdx.y, t = threadIdx.x;
  const float* src = g_P + (long)y * MSZ + (long)row * HIDN;
  __nv_bfloat16* dh = g_hi + (long)y * MSZ + (long)row * HIDN;
  __nv_bfloat16* dl = g_lo + (long)y * MSZ + (long)row * HIDN;
  if (y < 2) {
    const int h = t >> 5, i = t & 31;
    const int s = row & (SEQ - 1);
    float inv = exp2f(-(float)i * (13.287712379549449f / 32.f));
    float ang = (float)s * inv;
    float sn, cs;
    sincosf(ang, &sn, &cs);
    const int e = h * HDIM + i;
    float x1 = src[e], x2 = src[e + 32];
    float o1 = x1 * cs - x2 * sn;
    float o2 = x2 * cs + x1 * sn;
    __nv_bfloat16 h1 = __float2bfloat16_rn(o1), h2 = __float2bfloat16_rn(o2);
    dh[e]      = h1;
    dh[e + 32] = h2;
    dl[e]      = __float2bfloat16_rn(o1 - __bfloat162float(h1));
    dl[e + 32] = __float2bfloat16_rn(o2 - __bfloat162float(h2));
  } else {
#pragma unroll
    for (int j = 0; j < 2; j++) {
      const int e = t + j * 512;
      float v = src[e];
      __nv_bfloat16 hv = __float2bfloat16_rn(v);
      dh[e] = hv;
      dl[e] = __float2bfloat16_rn(v - __bfloat162float(hv));
    }
  }
}

// ---------------- tensor-core flash attention ------------------------------
// Block = (b, h, 64-q-rows); 4 warps, warp handles 16 q-rows x 64 keys x 64 hd.
__global__ __launch_bounds__(128, 1)
void attn_mma(const int* __restrict__ mask) {
  extern __shared__ __align__(128) char smem[];
  const uint32_t sb = (uint32_t)__cvta_generic_to_shared(smem);
  const int t = threadIdx.x, lane = t & 31, wid = t >> 5;
  const int b = blockIdx.z, h = blockIdx.y, q0 = blockIdx.x * 64;
  const int m0 = wid * 16;
  const __nv_bfloat16 *Qh = g_hi,            *Ql = g_lo;
  const __nv_bfloat16 *Kh = g_hi + MSZ,      *Kl = g_lo + MSZ;
  const __nv_bfloat16 *Vh = g_hi + 2L * MSZ, *Vl = g_lo + 2L * MSZ;

  // Q tile: rows are q0.., cols head-slice; pre-scaled in frags below? No —
  // Q was NOT pre-scaled; scale 1/8 is folded into softmax input via S scale.
  // Simpler: scale S after MMA (exactly matches reference order: scores/8).
#pragma unroll
  for (int j = 0; j < 4; j++) {
    const int idx = t + j * 128;
    const int r = idx >> 3, cc = idx & 7;
    const long off = (long)(b * SEQ + q0 + r) * HIDN + h * HDIM + cc * 8;
    const uint32_t so = sb + (uint32_t)(r * (ALD * 2) + cc * 16);
    cp16(so + SQH, Qh + off);
    cp16(so + SQL, Ql + off);
  }
  CP_COMMIT();
  CP_WAIT0();
  __syncthreads();

  uint32_t qh[4][4], ql[4][4];
  {
    const uint32_t base =
        sb + (uint32_t)((m0 + (lane & 15)) * (ALD * 2) + (lane >> 4) * 16);
#pragma unroll
    for (int kc = 0; kc < 4; kc++) {
      LDSM4(qh[kc], base + SQH + kc * 32);
      LDSM4(ql[kc], base + SQL + kc * 32);
    }
  }

  float o[8][4];
#pragma unroll
  for (int i = 0; i < 8; i++)
#pragma unroll
    for (int j = 0; j < 4; j++) o[i][j] = 0.f;
  float mA = -1e30f, mB = -1e30f, lA = 0.f, lB = 0.f;

  for (int kb = 0; kb < SEQ / 64; kb++) {
    const int k0 = kb * 64;
    __syncthreads();  // prior-iteration smem reads complete
#pragma unroll
    for (int j = 0; j < 4; j++) {
      const int idx = t + j * 128;
      const int r = idx >> 3, cc = idx & 7;
      const long off = (long)(b * SEQ + k0 + r) * HIDN + h * HDIM + cc * 8;
      const uint32_t so = sb + (uint32_t)(r * (ALD * 2) + cc * 16);
      cp16(so + SKH, Kh + off);
      cp16(so + SKL, Kl + off);
      cp16(so + SVH, Vh + off);
      cp16(so + SVL, Vl + off);
    }
    if (t < 64) ((int*)(smem + SMSK))[t] = mask[b * SEQ + k0 + t];
    CP_COMMIT();
    CP_WAIT0();
    __syncthreads();

    // S = Q K^T (3-term split), fp32 accum
    float s[8][4];
#pragma unroll
    for (int i = 0; i < 8; i++)
#pragma unroll
      for (int j = 0; j < 4; j++) s[i][j] = 0.f;
#pragma unroll
    for (int kc = 0; kc < 4; kc++) {
      const uint32_t base =
          sb + (uint32_t)((lane & 15) * (ALD * 2) + (lane >> 4) * 16 + kc * 32);
#pragma unroll
      for (int np = 0; np < 4; np++) {
        uint32_t kh4[4], kl4[4];
        const uint32_t a = base + (uint32_t)(np * 16 * (ALD * 2));
        LDSM4(kh4, a + SKH);
        LDSM4(kl4, a + SKL);
        MMA(s[2 * np],     qh[kc], kh4[0], kh4[2]);
        MMA(s[2 * np],     qh[kc], kl4[0], kl4[2]);
        MMA(s[2 * np],     ql[kc], kh4[0], kh4[2]);
        MMA(s[2 * np + 1], qh[kc], kh4[1], kh4[3]);
        MMA(s[2 * np + 1], qh[kc], kl4[1], kl4[3]);
        MMA(s[2 * np + 1], ql[kc], kh4[1], kh4[3]);
      }
    }

    // scale + mask (reference: scores/8 then masked -> 1e-10)
    const int cbase = (lane & 3) * 2;
    const int* smk = (const int*)(smem + SMSK);
#pragma unroll
    for (int nt = 0; nt < 8; nt++) {
      const int c = nt * 8 + cbase;
      const int mk0 = smk[c], mk1 = smk[c + 1];
      s[nt][0] = mk0 ? s[nt][0] * 0.125f : 1e-10f;
      s[nt][2] = mk0 ? s[nt][2] * 0.125f : 1e-10f;
      s[nt][1] = mk1 ? s[nt][1] * 0.125f : 1e-10f;
      s[nt][3] = mk1 ? s[nt][3] * 0.125f : 1e-10f;
    }

    // online softmax (rows rA = lane>>2, rB = rA+8)
    float bmA = -1e30f, bmB = -1e30f;
#pragma unroll
    for (int nt = 0; nt < 8; nt++) {
      bmA = fmaxf(bmA, fmaxf(s[nt][0], s[nt][1]));
      bmB = fmaxf(bmB, fmaxf(s[nt][2], s[nt][3]));
    }
#pragma unroll
    for (int off = 1; off <= 2; off <<= 1) {
      bmA = fmaxf(bmA, __shfl_xor_sync(0xffffffffu, bmA, off));
      bmB = fmaxf(bmB, __shfl_xor_sync(0xffffffffu, bmB, off));
    }
    const float mnA = fmaxf(mA, bmA), mnB = fmaxf(mB, bmB);
    const float cA = __expf(mA - mnA), cB = __expf(mB - mnB);
    mA = mnA; mB = mnB;
    float p[8][4];
    float sA = 0.f, sB = 0.f;
#pragma unroll
    for (int nt = 0; nt < 8; nt++) {
      p[nt][0] = __expf(s[nt][0] - mnA);
      p[nt][1] = __expf(s[nt][1] - mnA);
      p[nt][2] = __expf(s[nt][2] - mnB);
      p[nt][3] = __expf(s[nt][3] - mnB);
      sA += p[nt][0] + p[nt][1];
      sB += p[nt][2] + p[nt][3];
    }
#pragma unroll
    for (int off = 1; off <= 2; off <<= 1) {
      sA += __shfl_xor_sync(0xffffffffu, sA, off);
      sB += __shfl_xor_sync(0xffffffffu, sB, off);
    }
    lA = lA * cA + sA;
    lB = lB * cB + sB;
#pragma unroll
    for (int nt = 0; nt < 8; nt++) {
      o[nt][0] *= cA; o[nt][1] *= cA;
      o[nt][2] *= cB; o[nt][3] *= cB;
    }

    // pack P into A-fragments (hi/lo split)
    uint32_t ph[4][4], pl[4][4];
#pragma unroll
    for (int kc = 0; kc < 4; kc++) {
      split2(p[2 * kc][0],     p[2 * kc][1],     ph[kc][0], pl[kc][0]);
      split2(p[2 * kc][2],     p[2 * kc][3],     ph[kc][1], pl[kc][1]);
      split2(p[2 * kc + 1][0], p[2 * kc + 1][1], ph[kc][2], pl[kc][2]);
      split2(p[2 * kc + 1][2], p[2 * kc + 1][3], ph[kc][3], pl[kc][3]);
    }

    // O += P V (3-term split); V B-frags via trans ldmatrix
#pragma unroll
    for (int kc = 0; kc < 4; kc++) {
      const uint32_t vbase =
          sb + (uint32_t)((kc * 16 + (lane & 15)) * (ALD * 2) + (lane >> 4) * 16);
#pragma unroll
      for (int np = 0; np < 4; np++) {
        uint32_t vh4[4], vl4[4];
        const uint32_t a = vbase + (uint32_t)(np * 32);
        LDSM4T(vh4, a + SVH);
        LDSM4T(vl4, a + SVL);
        MMA(o[2 * np],     ph[kc], vh4[0], vh4[1]);
        MMA(o[2 * np],     ph[kc], vl4[0], vl4[1]);
        MMA(o[2 * np],     pl[kc], vh4[0], vh4[1]);
        MMA(o[2 * np + 1], ph[kc], vh4[2], vh4[3]);
        MMA(o[2 * np + 1], ph[kc], vl4[2], vl4[3]);
        MMA(o[2 * np + 1], pl[kc], vh4[2], vh4[3]);
      }
    }
  }

  // epilogue
  const float iA = 1.f / lA, iB = 1.f / lB;
  const long rA = (long)(b * SEQ + q0 + m0 + (lane >> 2));
  const long rB = rA + 8;
#pragma unroll
  for (int nt = 0; nt < 8; nt++) {
    const int col = h * HDIM + nt * 8 + (lane & 3) * 2;
    *(float2*)(g_X + rA * HIDN + col) = make_float2(o[nt][0] * iA, o[nt][1] * iA);
    *(float2*)(g_X + rB * HIDN + col) = make_float2(o[nt][2] * iB, o[nt][3] * iB);
  }
}

// ---------------- launch -----------------------------------------------------
extern "C" void kernel_launch(void* const* d_in, const int* in_sizes, int n_in,
                              void* d_out, int out_size) {
  const float* q   = (const float*)d_in[0];
  const float* k   = (const float*)d_in[1];
  const float* v   = (const float*)d_in[2];
  const float* g1q = (const float*)d_in[3];
  const float* b1q = (const float*)d_in[4];
  const float* g1k = (const float*)d_in[5];
  const float* b1k = (const float*)d_in[6];
  const float* g1v = (const float*)d_in[7];
  const float* b1v = (const float*)d_in[8];
  const float* Wq  = (const float*)d_in[9];
  const float* bq  = (const float*)d_in[10];
  const float* Wk  = (const float*)d_in[11];
  const float* bk  = (const float*)d_in[12];
  const float* Wv  = (const float*)d_in[13];
  const float* bv  = (const float*)d_in[14];
  const float* g2  = (const float*)d_in[15];
  const float* b2  = (const float*)d_in[16];
  const float* g3  = (const float*)d_in[17];
  const float* b3  = (const float*)d_in[18];
  const float* Wf  = (const float*)d_in[19];
  const float* bf  = (const float*)d_in[20];
  const int*  mask = (const int*)d_in[21];
  float* out = (float*)d_out;

  cudaFuncSetAttribute(gemm_mma, cudaFuncAttributeMaxDynamicSharedMemorySize, GEMM_SMEM);
  cudaFuncSetAttribute(attn_mma, cudaFuncAttributeMaxDynamicSharedMemorySize, ATTN_SMEM);

  // 0) weight split (hi/lo bf16)
  wconv_kernel<<<dim3(WSZ / 1024, 4), 256>>>(Wq, Wk, Wv, Wf);

  // 1) LayerNorms of q,k,v -> bf16 hi/lo slots 0..2
  ln_bf16_kernel<<<MROWS, 256>>>(q, g1q, b1q, 0, 0);
  ln_bf16_kernel<<<MROWS, 256>>>(k, g1k, b1k, 1, 0);
  ln_bf16_kernel<<<MROWS, 256>>>(v, g1v, b1v, 2, 0);

  // 2) Q/K/V projections via mma.sync (fused z=0..2) -> g_P fp32
  gemm_mma<<<dim3(HIDN / BN, MROWS / BM, 3), 256, GEMM_SMEM>>>(0, 0, 0, bq, bk, bv);

  // 3) RoPE + split Q,K,V -> bf16 hi/lo slots 0..2 (overwrites LN slots)
  rope_split_kernel<<<dim3(MROWS, 3), 512>>>();

  // 4) tensor-core flash attention -> g_X
  attn_mma<<<dim3(SEQ / 64, NHEAD, 4), 128, ATTN_SMEM>>>(mask);

  // 5) fx = LN(x) -> g_Fx (fp32) + slot 3 (bf16 hi/lo)
  ln_bf16_kernel<<<MROWS, 256>>>(nullptr, g2, b2, 3, 1);

  // 6) fo = relu(fx @ Wf^T + bf) via mma.sync
  gemm_mma<<<dim3(HIDN / BN, MROWS / BM, 1), 256, GEMM_SMEM>>>(3, 1, 1, bf, bf, bf);

  // 7) out = fx + LN(fo)
  ln_add_kernel<<<MROWS, 256>>>(g3, b3, out);
}

// round 6
// speedup vs baseline: 2.0770x; 1.1115x over previous
#include <cuda_runtime.h>
#include <cuda_bf16.h>
#include <math.h>
#include <stdint.h>

#define HIDN 1024
#define MROWS 4096
#define SEQ 1024
#define NHEAD 16
#define HDIM 64
#define MSZ (MROWS * HIDN)
#define WSZ (HIDN * HIDN)

// mma.sync GEMM tiling
#define BM 128
#define BN 128
#define BK 32
#define NS (HIDN / BK)                 // 32 k-stages
#define LDT 40                         // row stride in bf16 elems (32 + 8 pad)
#define TBYTES (128 * LDT * 2)         // 10240 bytes per tensor tile
#define OFF_AHI 0
#define OFF_ALO (1 * TBYTES)
#define OFF_BHI (2 * TBYTES)
#define OFF_BLO (3 * TBYTES)
#define SSTRIDE (4 * TBYTES)           // 40960 per stage
#define GEMM_SMEM (2 * SSTRIDE)        // 81920, 2-stage => 2 CTAs/SM

// attention tiling (double-buffered K/V)
#define ALD 72                         // 64 + 8 pad bf16 elems per row
#define ATILE_B (64 * ALD * 2)         // 9216 bytes per 64x64 bf16 tile
#define SQH 0
#define SQL (1 * ATILE_B)
#define SKH(st) (2 * ATILE_B + (st) * 4 * ATILE_B)
#define SKL(st) (SKH(st) + ATILE_B)
#define SVH(st) (SKH(st) + 2 * ATILE_B)
#define SVL(st) (SKH(st) + 3 * ATILE_B)
#define SMSK(st) (10 * ATILE_B + (st) * 256)
#define ATTN_SMEM (10 * ATILE_B + 512)   // 92672 => 2 CTAs/SM

// ---------------- scratch (device globals; no allocation allowed) ----------
__device__ __align__(16) __nv_bfloat16 g_hi[4L * MSZ];   // hi: LN outs, then rope'd Q/K/V
__device__ __align__(16) __nv_bfloat16 g_lo[4L * MSZ];   // lo residuals
__device__ __align__(16) __nv_bfloat16 g_Whi[4L * WSZ];  // weights hi (0=Wq,1=Wk,2=Wv,3=Wf)
__device__ __align__(16) __nv_bfloat16 g_Wlo[4L * WSZ];  // weights lo
__device__ __align__(16) float g_P [3L * MSZ];  // Q,K,V projections fp32
__device__ __align__(16) float g_X [MSZ];       // attention output
__device__ __align__(16) float g_Fx[MSZ];       // LN2 output (residual)
__device__ __align__(16) float g_Fo[MSZ];       // relu(ffn)

// ---------------- PTX helpers ----------------
__device__ __forceinline__ void cp16(uint32_t dst, const void* src) {
  asm volatile("cp.async.cg.shared.global [%0], [%1], 16;\n"
               :: "r"(dst), "l"(__cvta_generic_to_global(src)) : "memory");
}
#define CP_COMMIT() asm volatile("cp.async.commit_group;" ::: "memory")
#define CP_WAIT1()  asm volatile("cp.async.wait_group 1;" ::: "memory")
#define CP_WAIT0()  asm volatile("cp.async.wait_group 0;" ::: "memory")

#define LDSM4(r, addr) asm volatile( \
  "ldmatrix.sync.aligned.m8n8.x4.shared.b16 {%0,%1,%2,%3}, [%4];" \
  : "=r"((r)[0]), "=r"((r)[1]), "=r"((r)[2]), "=r"((r)[3]) : "r"(addr))

#define LDSM4T(r, addr) asm volatile( \
  "ldmatrix.sync.aligned.m8n8.x4.trans.shared.b16 {%0,%1,%2,%3}, [%4];" \
  : "=r"((r)[0]), "=r"((r)[1]), "=r"((r)[2]), "=r"((r)[3]) : "r"(addr))

#define MMA(acc, a, b0, b1) asm volatile( \
  "mma.sync.aligned.m16n8k16.row.col.f32.bf16.bf16.f32 " \
  "{%0,%1,%2,%3}, {%4,%5,%6,%7}, {%8,%9}, {%0,%1,%2,%3};" \
  : "+f"((acc)[0]), "+f"((acc)[1]), "+f"((acc)[2]), "+f"((acc)[3]) \
  : "r"((a)[0]), "r"((a)[1]), "r"((a)[2]), "r"((a)[3]), "r"(b0), "r"(b1))

__device__ __forceinline__ void split2(float a, float b, uint32_t& hi, uint32_t& lo) {
  __nv_bfloat16 ha = __float2bfloat16_rn(a), hb = __float2bfloat16_rn(b);
  __nv_bfloat162 h(ha, hb);
  __nv_bfloat162 l(__float2bfloat16_rn(a - __bfloat162float(ha)),
                   __float2bfloat16_rn(b - __bfloat162float(hb)));
  hi = *(uint32_t*)&h;
  lo = *(uint32_t*)&l;
}

// ---------------- reductions ----------------
__device__ __forceinline__ float warpSum(float v) {
#pragma unroll
  for (int o = 16; o; o >>= 1) v += __shfl_xor_sync(0xffffffffu, v, o);
  return v;
}
__device__ __forceinline__ float blockSum(float partial, float* sh) {
  __syncthreads();
  float w = warpSum(partial);
  if ((threadIdx.x & 31) == 0) sh[threadIdx.x >> 5] = w;
  __syncthreads();
  float tot = 0.f;
#pragma unroll
  for (int i = 0; i < 8; i++) tot += sh[i];
  return tot;
}

// ---------------- weight split: fp32 -> bf16 hi/lo -------------------------
__global__ __launch_bounds__(256)
void wconv_kernel(const float* __restrict__ w0, const float* __restrict__ w1,
                  const float* __restrict__ w2, const float* __restrict__ w3) {
  const float* src = blockIdx.y == 0 ? w0 : blockIdx.y == 1 ? w1
                   : blockIdx.y == 2 ? w2 : w3;
  const long base = (long)blockIdx.y * WSZ;
  const long i = ((long)blockIdx.x * 256 + threadIdx.x) * 4;
  float4 v = *(const float4*)(src + i);
  uint32_t h0, l0, h1, l1;
  split2(v.x, v.y, h0, l0);
  split2(v.z, v.w, h1, l1);
  *(uint32_t*)(g_Whi + base + i)     = h0;
  *(uint32_t*)(g_Whi + base + i + 2) = h1;
  *(uint32_t*)(g_Wlo + base + i)     = l0;
  *(uint32_t*)(g_Wlo + base + i + 2) = l1;
}

// ---------------- LayerNorm -> bf16 hi/lo (optionally fp32 g_Fx) -----------
__global__ __launch_bounds__(256)
void ln_bf16_kernel(const float* __restrict__ xext, const float* __restrict__ g,
                    const float* __restrict__ b, int slot, int writeFx) {
  __shared__ float sh[8];
  const float* x = xext ? xext : g_X;
  const int row = blockIdx.x, t = threadIdx.x;
  float4 v = ((const float4*)(x + (long)row * HIDN))[t];
  float mean = blockSum(v.x + v.y + v.z + v.w, sh) * (1.f / HIDN);
  float dx = v.x - mean, dy = v.y - mean, dz = v.z - mean, dw = v.w - mean;
  float var = blockSum(dx * dx + dy * dy + dz * dz + dw * dw, sh) * (1.f / HIDN);
  float rstd = rsqrtf(var + 1e-5f);
  float4 gv = ((const float4*)g)[t];
  float4 bv = ((const float4*)b)[t];
  float4 o = make_float4(dx * rstd * gv.x + bv.x, dy * rstd * gv.y + bv.y,
                         dz * rstd * gv.z + bv.z, dw * rstd * gv.w + bv.w);
  if (writeFx) ((float4*)(g_Fx + (long)row * HIDN))[t] = o;
  const long off = (long)slot * MSZ + (long)row * HIDN + t * 4;
  uint32_t h0, l0, h1, l1;
  split2(o.x, o.y, h0, l0);
  split2(o.z, o.w, h1, l1);
  *(uint32_t*)(g_hi + off)     = h0;
  *(uint32_t*)(g_hi + off + 2) = h1;
  *(uint32_t*)(g_lo + off)     = l0;
  *(uint32_t*)(g_lo + off + 2) = l1;
}

// out = g_Fx + LN(g_Fo)*g3 + b3
__global__ __launch_bounds__(256)
void ln_add_kernel(const float* __restrict__ g, const float* __restrict__ b,
                   float* __restrict__ out) {
  __shared__ float sh[8];
  const int row = blockIdx.x, t = threadIdx.x;
  float4 v = ((const float4*)(g_Fo + (long)row * HIDN))[t];
  float mean = blockSum(v.x + v.y + v.z + v.w, sh) * (1.f / HIDN);
  float dx = v.x - mean, dy = v.y - mean, dz = v.z - mean, dw = v.w - mean;
  float var = blockSum(dx * dx + dy * dy + dz * dz + dw * dw, sh) * (1.f / HIDN);
  float rstd = rsqrtf(var + 1e-5f);
  float4 gv = ((const float4*)g)[t];
  float4 bv = ((const float4*)b)[t];
  float4 fx = ((const float4*)(g_Fx + (long)row * HIDN))[t];
  float4 o = make_float4(fx.x + dx * rstd * gv.x + bv.x,
                         fx.y + dy * rstd * gv.y + bv.y,
                         fx.z + dz * rstd * gv.z + bv.z,
                         fx.w + dw * rstd * gv.w + bv.w);
  ((float4*)(out + (long)row * HIDN))[t] = o;
}

// ---------------- split-bf16 mma.sync GEMM: C = A @ W^T + bias -------------
// 128x128 block, 8 warps (2x4), 2-stage cp.async, 2 CTAs/SM.
__device__ __forceinline__ void gemm_load_stage(
    uint32_t sbase, const __nv_bfloat16* Ah, const __nv_bfloat16* Al,
    const __nv_bfloat16* Bh, const __nv_bfloat16* Bl,
    int row0, int col0, int k0, int t) {
#pragma unroll
  for (int j = 0; j < 2; j++) {
    const int idx = t + j * 256;
    const int r = idx >> 2, cc = idx & 3;
    const uint32_t so = sbase + (uint32_t)(r * (LDT * 2) + cc * 16);
    const long ga = (long)(row0 + r) * HIDN + k0 + cc * 8;
    const long gb = (long)(col0 + r) * HIDN + k0 + cc * 8;
    cp16(so + OFF_AHI, Ah + ga);
    cp16(so + OFF_ALO, Al + ga);
    cp16(so + OFF_BHI, Bh + gb);
    cp16(so + OFF_BLO, Bl + gb);
  }
}

__global__ __launch_bounds__(256, 2)
void gemm_mma(int aslot0, int cdst, int relu,
              const float* __restrict__ bias0, const float* __restrict__ bias1,
              const float* __restrict__ bias2) {
  extern __shared__ __align__(128) char smem[];
  const int z = blockIdx.z;
  const int slot = aslot0 + z;
  const __nv_bfloat16* Ah = g_hi  + (long)slot * MSZ;
  const __nv_bfloat16* Al = g_lo  + (long)slot * MSZ;
  const __nv_bfloat16* Bh = g_Whi + (long)slot * WSZ;
  const __nv_bfloat16* Bl = g_Wlo + (long)slot * WSZ;
  float* C = cdst ? g_Fo : (g_P + (long)z * MSZ);
  const float* bias = (z == 0) ? bias0 : ((z == 1) ? bias1 : bias2);

  const int t = threadIdx.x;
  const int wid = t >> 5, lane = t & 31;
  const int wm = wid >> 2, wn = wid & 3;
  const int row0 = blockIdx.y * BM, col0 = blockIdx.x * BN;
  const uint32_t sb = (uint32_t)__cvta_generic_to_shared(smem);

  float acc[4][4][4];
#pragma unroll
  for (int i = 0; i < 4; i++)
#pragma unroll
    for (int j = 0; j < 4; j++)
#pragma unroll
      for (int r = 0; r < 4; r++) acc[i][j][r] = 0.f;

  gemm_load_stage(sb, Ah, Al, Bh, Bl, row0, col0, 0, t);
  CP_COMMIT();

  const uint32_t aOff = (uint32_t)((wm * 64 + (lane & 15)) * (LDT * 2) + (lane >> 4) * 16);
  const uint32_t bOff = (uint32_t)((wn * 32 + (lane & 15)) * (LDT * 2) + (lane >> 4) * 16);

  for (int s = 0; s < NS; s++) {
    if (s + 1 < NS) {
      gemm_load_stage(sb + (uint32_t)(((s + 1) & 1) * SSTRIDE),
                      Ah, Al, Bh, Bl, row0, col0, (s + 1) * BK, t);
    }
    CP_COMMIT();
    CP_WAIT1();       // stage s resident (only s+1's group may still be pending)
    __syncthreads();
    const uint32_t st = sb + (uint32_t)((s & 1) * SSTRIDE);
#pragma unroll
    for (int kk = 0; kk < 2; kk++) {
      uint32_t ah[4][4], al[4][4];
#pragma unroll
      for (int mi = 0; mi < 4; mi++) {
        const uint32_t a = st + aOff + (uint32_t)(mi * 16 * (LDT * 2) + kk * 32);
        LDSM4(ah[mi], a + OFF_AHI);
        LDSM4(al[mi], a + OFF_ALO);
      }
      uint32_t bh[2][4], bl[2][4];
#pragma unroll
      for (int bn = 0; bn < 2; bn++) {
        const uint32_t a = st + bOff + (uint32_t)(bn * 16 * (LDT * 2) + kk * 32);
        LDSM4(bh[bn], a + OFF_BHI);
        LDSM4(bl[bn], a + OFF_BLO);
      }
#pragma unroll
      for (int mi = 0; mi < 4; mi++) {
#pragma unroll
        for (int bn = 0; bn < 2; bn++) {
          const int ni = bn * 2;
          MMA(acc[mi][ni],     ah[mi], bh[bn][0], bh[bn][2]);
          MMA(acc[mi][ni],     ah[mi], bl[bn][0], bl[bn][2]);
          MMA(acc[mi][ni],     al[mi], bh[bn][0], bh[bn][2]);
          MMA(acc[mi][ni + 1], ah[mi], bh[bn][1], bh[bn][3]);
          MMA(acc[mi][ni + 1], ah[mi], bl[bn][1], bl[bn][3]);
          MMA(acc[mi][ni + 1], al[mi], bh[bn][1], bh[bn][3]);
        }
      }
    }
    __syncthreads();  // stage s fully consumed before next prefetch overwrites
  }

#pragma unroll
  for (int mi = 0; mi < 4; mi++) {
    const long r = row0 + wm * 64 + mi * 16 + (lane >> 2);
#pragma unroll
    for (int ni = 0; ni < 4; ni++) {
      const int c = col0 + wn * 32 + ni * 8 + (lane & 3) * 2;
      float2 bv = *(const float2*)(bias + c);
      float v0 = acc[mi][ni][0] + bv.x, v1 = acc[mi][ni][1] + bv.y;
      float v2 = acc[mi][ni][2] + bv.x, v3 = acc[mi][ni][3] + bv.y;
      if (relu) {
        v0 = fmaxf(v0, 0.f); v1 = fmaxf(v1, 0.f);
        v2 = fmaxf(v2, 0.f); v3 = fmaxf(v3, 0.f);
      }
      *(float2*)(C + r * HIDN + c)       = make_float2(v0, v1);
      *(float2*)(C + (r + 8) * HIDN + c) = make_float2(v2, v3);
    }
  }
}

// ---------------- RoPE + split to bf16 hi/lo slots 0,1,2 -------------------
__global__ __launch_bounds__(512)
void rope_split_kernel() {
  const int row = blockIdx.x, y = blockIdx.y, t = threadIdx.x;
  const float* src = g_P + (long)y * MSZ + (long)row * HIDN;
  __nv_bfloat16* dh = g_hi + (long)y * MSZ + (long)row * HIDN;
  __nv_bfloat16* dl = g_lo + (long)y * MSZ + (long)row * HIDN;
  if (y < 2) {
    const int h = t >> 5, i = t & 31;
    const int s = row & (SEQ - 1);
    float inv = exp2f(-(float)i * (13.287712379549449f / 32.f));
    float ang = (float)s * inv;
    float sn, cs;
    sincosf(ang, &sn, &cs);
    const int e = h * HDIM + i;
    float x1 = src[e], x2 = src[e + 32];
    float o1 = x1 * cs - x2 * sn;
    float o2 = x2 * cs + x1 * sn;
    __nv_bfloat16 h1 = __float2bfloat16_rn(o1), h2 = __float2bfloat16_rn(o2);
    dh[e]      = h1;
    dh[e + 32] = h2;
    dl[e]      = __float2bfloat16_rn(o1 - __bfloat162float(h1));
    dl[e + 32] = __float2bfloat16_rn(o2 - __bfloat162float(h2));
  } else {
#pragma unroll
    for (int j = 0; j < 2; j++) {
      const int e = t + j * 512;
      float v = src[e];
      __nv_bfloat16 hv = __float2bfloat16_rn(v);
      dh[e] = hv;
      dl[e] = __float2bfloat16_rn(v - __bfloat162float(hv));
    }
  }
}

// ---------------- tensor-core flash attention (double-buffered K/V) --------
__device__ __forceinline__ void attn_load_kv(
    uint32_t sb, int st, const __nv_bfloat16* Kh, const __nv_bfloat16* Kl,
    const __nv_bfloat16* Vh, const __nv_bfloat16* Vl,
    const int* mask, char* smem, int b, int h, int k0, int t) {
#pragma unroll
  for (int j = 0; j < 4; j++) {
    const int idx = t + j * 128;
    const int r = idx >> 3, cc = idx & 7;
    const long off = (long)(b * SEQ + k0 + r) * HIDN + h * HDIM + cc * 8;
    const uint32_t so = sb + (uint32_t)(r * (ALD * 2) + cc * 16);
    cp16(so + SKH(st), Kh + off);
    cp16(so + SKL(st), Kl + off);
    cp16(so + SVH(st), Vh + off);
    cp16(so + SVL(st), Vl + off);
  }
  if (t < 64) ((int*)(smem + SMSK(st)))[t] = mask[b * SEQ + k0 + t];
}

__global__ __launch_bounds__(128, 2)
void attn_mma(const int* __restrict__ mask) {
  extern __shared__ __align__(128) char smem[];
  const uint32_t sb = (uint32_t)__cvta_generic_to_shared(smem);
  const int t = threadIdx.x, lane = t & 31, wid = t >> 5;
  const int b = blockIdx.z, h = blockIdx.y, q0 = blockIdx.x * 64;
  const int m0 = wid * 16;
  const __nv_bfloat16 *Qh = g_hi,            *Ql = g_lo;
  const __nv_bfloat16 *Kh = g_hi + MSZ,      *Kl = g_lo + MSZ;
  const __nv_bfloat16 *Vh = g_hi + 2L * MSZ, *Vl = g_lo + 2L * MSZ;

#pragma unroll
  for (int j = 0; j < 4; j++) {
    const int idx = t + j * 128;
    const int r = idx >> 3, cc = idx & 7;
    const long off = (long)(b * SEQ + q0 + r) * HIDN + h * HDIM + cc * 8;
    const uint32_t so = sb + (uint32_t)(r * (ALD * 2) + cc * 16);
    cp16(so + SQH, Qh + off);
    cp16(so + SQL, Ql + off);
  }
  attn_load_kv(sb, 0, Kh, Kl, Vh, Vl, mask, smem, b, h, 0, t);
  CP_COMMIT();
  CP_WAIT0();
  __syncthreads();

  uint32_t qh[4][4], ql[4][4];
  {
    const uint32_t base =
        sb + (uint32_t)((m0 + (lane & 15)) * (ALD * 2) + (lane >> 4) * 16);
#pragma unroll
    for (int kc = 0; kc < 4; kc++) {
      LDSM4(qh[kc], base + SQH + kc * 32);
      LDSM4(ql[kc], base + SQL + kc * 32);
    }
  }

  float o[8][4];
#pragma unroll
  for (int i = 0; i < 8; i++)
#pragma unroll
    for (int j = 0; j < 4; j++) o[i][j] = 0.f;
  float mA = -1e30f, mB = -1e30f, lA = 0.f, lB = 0.f;

  for (int kb = 0; kb < SEQ / 64; kb++) {
    const int st = kb & 1;
    if (kb + 1 < SEQ / 64) {  // prefetch next K/V block into other stage
      attn_load_kv(sb, st ^ 1, Kh, Kl, Vh, Vl, mask, smem, b, h,
                   (kb + 1) * 64, t);
    }
    CP_COMMIT();
    CP_WAIT1();       // current stage resident
    __syncthreads();

    // S = Q K^T (3-term split), fp32 accum
    float s[8][4];
#pragma unroll
    for (int i = 0; i < 8; i++)
#pragma unroll
      for (int j = 0; j < 4; j++) s[i][j] = 0.f;
#pragma unroll
    for (int kc = 0; kc < 4; kc++) {
      const uint32_t base =
          sb + (uint32_t)((lane & 15) * (ALD * 2) + (lane >> 4) * 16 + kc * 32);
#pragma unroll
      for (int np = 0; np < 4; np++) {
        uint32_t kh4[4], kl4[4];
        const uint32_t a = base + (uint32_t)(np * 16 * (ALD * 2));
        LDSM4(kh4, a + SKH(st));
        LDSM4(kl4, a + SKL(st));
        MMA(s[2 * np],     qh[kc], kh4[0], kh4[2]);
        MMA(s[2 * np],     qh[kc], kl4[0], kl4[2]);
        MMA(s[2 * np],     ql[kc], kh4[0], kh4[2]);
        MMA(s[2 * np + 1], qh[kc], kh4[1], kh4[3]);
        MMA(s[2 * np + 1], qh[kc], kl4[1], kl4[3]);
        MMA(s[2 * np + 1], ql[kc], kh4[1], kh4[3]);
      }
    }

    // scale + mask (reference: scores/8 then masked -> 1e-10)
    const int cbase = (lane & 3) * 2;
    const int* smk = (const int*)(smem + SMSK(st));
#pragma unroll
    for (int nt = 0; nt < 8; nt++) {
      const int c = nt * 8 + cbase;
      const int mk0 = smk[c], mk1 = smk[c + 1];
      s[nt][0] = mk0 ? s[nt][0] * 0.125f : 1e-10f;
      s[nt][2] = mk0 ? s[nt][2] * 0.125f : 1e-10f;
      s[nt][1] = mk1 ? s[nt][1] * 0.125f : 1e-10f;
      s[nt][3] = mk1 ? s[nt][3] * 0.125f : 1e-10f;
    }

    // online softmax (rows rA = lane>>2, rB = rA+8)
    float bmA = -1e30f, bmB = -1e30f;
#pragma unroll
    for (int nt = 0; nt < 8; nt++) {
      bmA = fmaxf(bmA, fmaxf(s[nt][0], s[nt][1]));
      bmB = fmaxf(bmB, fmaxf(s[nt][2], s[nt][3]));
    }
#pragma unroll
    for (int off = 1; off <= 2; off <<= 1) {
      bmA = fmaxf(bmA, __shfl_xor_sync(0xffffffffu, bmA, off));
      bmB = fmaxf(bmB, __shfl_xor_sync(0xffffffffu, bmB, off));
    }
    const float mnA = fmaxf(mA, bmA), mnB = fmaxf(mB, bmB);
    const float cA = __expf(mA - mnA), cB = __expf(mB - mnB);
    mA = mnA; mB = mnB;
    float p[8][4];
    float sA = 0.f, sB = 0.f;
#pragma unroll
    for (int nt = 0; nt < 8; nt++) {
      p[nt][0] = __expf(s[nt][0] - mnA);
      p[nt][1] = __expf(s[nt][1] - mnA);
      p[nt][2] = __expf(s[nt][2] - mnB);
      p[nt][3] = __expf(s[nt][3] - mnB);
      sA += p[nt][0] + p[nt][1];
      sB += p[nt][2] + p[nt][3];
    }
#pragma unroll
    for (int off = 1; off <= 2; off <<= 1) {
      sA += __shfl_xor_sync(0xffffffffu, sA, off);
      sB += __shfl_xor_sync(0xffffffffu, sB, off);
    }
    lA = lA * cA + sA;
    lB = lB * cB + sB;
#pragma unroll
    for (int nt = 0; nt < 8; nt++) {
      o[nt][0] *= cA; o[nt][1] *= cA;
      o[nt][2] *= cB; o[nt][3] *= cB;
    }

    // pack P into A-fragments (hi/lo split)
    uint32_t ph[4][4], pl[4][4];
#pragma unroll
    for (int kc = 0; kc < 4; kc++) {
      split2(p[2 * kc][0],     p[2 * kc][1],     ph[kc][0], pl[kc][0]);
      split2(p[2 * kc][2],     p[2 * kc][3],     ph[kc][1], pl[kc][1]);
      split2(p[2 * kc + 1][0], p[2 * kc + 1][1], ph[kc][2], pl[kc][2]);
      split2(p[2 * kc + 1][2], p[2 * kc + 1][3], ph[kc][3], pl[kc][3]);
    }

    // O += P V (3-term split); V B-frags via trans ldmatrix
#pragma unroll
    for (int kc = 0; kc < 4; kc++) {
      const uint32_t vbase =
          sb + (uint32_t)((kc * 16 + (lane & 15)) * (ALD * 2) + (lane >> 4) * 16);
#pragma unroll
      for (int np = 0; np < 4; np++) {
        uint32_t vh4[4], vl4[4];
        const uint32_t a = vbase + (uint32_t)(np * 32);
        LDSM4T(vh4, a + SVH(st));
        LDSM4T(vl4, a + SVL(st));
        MMA(o[2 * np],     ph[kc], vh4[0], vh4[1]);
        MMA(o[2 * np],     ph[kc], vl4[0], vl4[1]);
        MMA(o[2 * np],     pl[kc], vh4[0], vh4[1]);
        MMA(o[2 * np + 1], ph[kc], vh4[2], vh4[3]);
        MMA(o[2 * np + 1], ph[kc], vl4[2], vl4[3]);
        MMA(o[2 * np + 1], pl[kc], vh4[2], vh4[3]);
      }
    }
    __syncthreads();  // stage consumed before its next overwrite
  }

  // epilogue
  const float iA = 1.f / lA, iB = 1.f / lB;
  const long rA = (long)(b * SEQ + q0 + m0 + (lane >> 2));
  const long rB = rA + 8;
#pragma unroll
  for (int nt = 0; nt < 8; nt++) {
    const int col = h * HDIM + nt * 8 + (lane & 3) * 2;
    *(float2*)(g_X + rA * HIDN + col) = make_float2(o[nt][0] * iA, o[nt][1] * iA);
    *(float2*)(g_X + rB * HIDN + col) = make_float2(o[nt][2] * iB, o[nt][3] * iB);
  }
}

// ---------------- launch -----------------------------------------------------
extern "C" void kernel_launch(void* const* d_in, const int* in_sizes, int n_in,
                              void* d_out, int out_size) {
  const float* q   = (const float*)d_in[0];
  const float* k   = (const float*)d_in[1];
  const float* v   = (const float*)d_in[2];
  const float* g1q = (const float*)d_in[3];
  const float* b1q = (const float*)d_in[4];
  const float* g1k = (const float*)d_in[5];
  const float* b1k = (const float*)d_in[6];
  const float* g1v = (const float*)d_in[7];
  const float* b1v = (const float*)d_in[8];
  const float* Wq  = (const float*)d_in[9];
  const float* bq  = (const float*)d_in[10];
  const float* Wk  = (const float*)d_in[11];
  const float* bk  = (const float*)d_in[12];
  const float* Wv  = (const float*)d_in[13];
  const float* bv  = (const float*)d_in[14];
  const float* g2  = (const float*)d_in[15];
  const float* b2  = (const float*)d_in[16];
  const float* g3  = (const float*)d_in[17];
  const float* b3  = (const float*)d_in[18];
  const float* Wf  = (const float*)d_in[19];
  const float* bf  = (const float*)d_in[20];
  const int*  mask = (const int*)d_in[21];
  float* out = (float*)d_out;

  cudaFuncSetAttribute(gemm_mma, cudaFuncAttributeMaxDynamicSharedMemorySize, GEMM_SMEM);
  cudaFuncSetAttribute(attn_mma, cudaFuncAttributeMaxDynamicSharedMemorySize, ATTN_SMEM);

  // 0) weight split (hi/lo bf16)
  wconv_kernel<<<dim3(WSZ / 1024, 4), 256>>>(Wq, Wk, Wv, Wf);

  // 1) LayerNorms of q,k,v -> bf16 hi/lo slots 0..2
  ln_bf16_kernel<<<MROWS, 256>>>(q, g1q, b1q, 0, 0);
  ln_bf16_kernel<<<MROWS, 256>>>(k, g1k, b1k, 1, 0);
  ln_bf16_kernel<<<MROWS, 256>>>(v, g1v, b1v, 2, 0);

  // 2) Q/K/V projections via mma.sync (fused z=0..2) -> g_P fp32
  gemm_mma<<<dim3(HIDN / BN, MROWS / BM, 3), 256, GEMM_SMEM>>>(0, 0, 0, bq, bk, bv);

  // 3) RoPE + split Q,K,V -> bf16 hi/lo slots 0..2
  rope_split_kernel<<<dim3(MROWS, 3), 512>>>();

  // 4) tensor-core flash attention -> g_X
  attn_mma<<<dim3(SEQ / 64, NHEAD, 4), 128, ATTN_SMEM>>>(mask);

  // 5) fx = LN(x) -> g_Fx (fp32) + slot 3 (bf16 hi/lo)
  ln_bf16_kernel<<<MROWS, 256>>>(nullptr, g2, b2, 3, 1);

  // 6) fo = relu(fx @ Wf^T + bf) via mma.sync
  gemm_mma<<<dim3(HIDN / BN, MROWS / BM, 1), 256, GEMM_SMEM>>>(3, 1, 1, bf, bf, bf);

  // 7) out = fx + LN(fo)
  ln_add_kernel<<<MROWS, 256>>>(g3, b3, out);
}

// round 7
// speedup vs baseline: 2.9872x; 1.4382x over previous
#include <cuda_runtime.h>
#include <cuda_fp16.h>
#include <math.h>
#include <stdint.h>

#define HIDN 1024
#define MROWS 4096
#define SEQ 1024
#define NHEAD 16
#define HDIM 64
#define MSZ (MROWS * HIDN)
#define WSZ (HIDN * HIDN)

// mma.sync GEMM tiling (fp16 2-term: A hi-only, B hi+lo)
#define BM 128
#define BN 128
#define BK 32
#define NS (HIDN / BK)                 // 32 k-stages
#define LDT 40                         // row stride in fp16 elems (32 + 8 pad)
#define TBYTES (128 * LDT * 2)         // 10240 bytes per tile
#define OFF_A 0
#define OFF_BHI (1 * TBYTES)
#define OFF_BLO (2 * TBYTES)
#define SSTRIDE (3 * TBYTES)           // 30720 per stage
#define GEMM_SMEM (2 * SSTRIDE)        // 61440, 2-stage

// attention tiling (Q hi, K hi+lo, V hi; double-buffered K/V)
#define ALD 72                         // 64 + 8 pad fp16 elems per row
#define ATILE_B (64 * ALD * 2)         // 9216 bytes per 64x64 tile
#define SQH 0
#define SKH(st) (ATILE_B * (1 + (st) * 3))
#define SKL(st) (SKH(st) + ATILE_B)
#define SVH(st) (SKH(st) + 2 * ATILE_B)
#define SMSK(st) (7 * ATILE_B + (st) * 256)
#define ATTN_SMEM (7 * ATILE_B + 512)  // 65024 => 3 CTAs/SM

// ---------------- scratch (device globals; no allocation allowed) ----------
__device__ __align__(16) __half g_hi[4L * MSZ];   // hi activations (0=Q,1=K,2=V,3=Fx)
__device__ __align__(16) __half g_lo[4L * MSZ];   // lo residuals (only K slot used)
__device__ __align__(16) __half g_Whi[4L * WSZ];  // weights hi (0=Wq,1=Wk,2=Wv,3=Wf)
__device__ __align__(16) __half g_Wlo[4L * WSZ];  // weights lo
__device__ __align__(16) float g_P [3L * MSZ];  // Q,K,V projections fp32
__device__ __align__(16) float g_X [MSZ];       // attention output
__device__ __align__(16) float g_Fx[MSZ];       // LN2 output (residual)
__device__ __align__(16) float g_Fo[MSZ];       // relu(ffn)

// ---------------- PTX helpers ----------------
__device__ __forceinline__ void cp16(uint32_t dst, const void* src) {
  asm volatile("cp.async.cg.shared.global [%0], [%1], 16;\n"
               :: "r"(dst), "l"(__cvta_generic_to_global(src)) : "memory");
}
#define CP_COMMIT() asm volatile("cp.async.commit_group;" ::: "memory")
#define CP_WAIT1()  asm volatile("cp.async.wait_group 1;" ::: "memory")
#define CP_WAIT0()  asm volatile("cp.async.wait_group 0;" ::: "memory")

#define LDSM4(r, addr) asm volatile( \
  "ldmatrix.sync.aligned.m8n8.x4.shared.b16 {%0,%1,%2,%3}, [%4];" \
  : "=r"((r)[0]), "=r"((r)[1]), "=r"((r)[2]), "=r"((r)[3]) : "r"(addr))

#define LDSM4T(r, addr) asm volatile( \
  "ldmatrix.sync.aligned.m8n8.x4.trans.shared.b16 {%0,%1,%2,%3}, [%4];" \
  : "=r"((r)[0]), "=r"((r)[1]), "=r"((r)[2]), "=r"((r)[3]) : "r"(addr))

#define MMA(acc, a, b0, b1) asm volatile( \
  "mma.sync.aligned.m16n8k16.row.col.f32.f16.f16.f32 " \
  "{%0,%1,%2,%3}, {%4,%5,%6,%7}, {%8,%9}, {%0,%1,%2,%3};" \
  : "+f"((acc)[0]), "+f"((acc)[1]), "+f"((acc)[2]), "+f"((acc)[3]) \
  : "r"((a)[0]), "r"((a)[1]), "r"((a)[2]), "r"((a)[3]), "r"(b0), "r"(b1))

__device__ __forceinline__ uint32_t pack_h2(float a, float b) {
  __half2 h(__float2half_rn(a), __float2half_rn(b));
  return *(uint32_t*)&h;
}
__device__ __forceinline__ void split2h(float a, float b, uint32_t& hi, uint32_t& lo) {
  __half ha = __float2half_rn(a), hb = __float2half_rn(b);
  __half2 h(ha, hb);
  __half2 l(__float2half_rn(a - __half2float(ha)),
            __float2half_rn(b - __half2float(hb)));
  hi = *(uint32_t*)&h;
  lo = *(uint32_t*)&l;
}

// ---------------- reductions ----------------
__device__ __forceinline__ float warpSum(float v) {
#pragma unroll
  for (int o = 16; o; o >>= 1) v += __shfl_xor_sync(0xffffffffu, v, o);
  return v;
}
__device__ __forceinline__ float blockSum(float partial, float* sh) {
  __syncthreads();
  float w = warpSum(partial);
  if ((threadIdx.x & 31) == 0) sh[threadIdx.x >> 5] = w;
  __syncthreads();
  float tot = 0.f;
#pragma unroll
  for (int i = 0; i < 8; i++) tot += sh[i];
  return tot;
}

// ---------------- weight split: fp32 -> fp16 hi/lo -------------------------
__global__ __launch_bounds__(256)
void wconv_kernel(const float* __restrict__ w0, const float* __restrict__ w1,
                  const float* __restrict__ w2, const float* __restrict__ w3) {
  const float* src = blockIdx.y == 0 ? w0 : blockIdx.y == 1 ? w1
                   : blockIdx.y == 2 ? w2 : w3;
  const long base = (long)blockIdx.y * WSZ;
  const long i = ((long)blockIdx.x * 256 + threadIdx.x) * 4;
  float4 v = *(const float4*)(src + i);
  uint32_t h0, l0, h1, l1;
  split2h(v.x, v.y, h0, l0);
  split2h(v.z, v.w, h1, l1);
  *(uint32_t*)(g_Whi + base + i)     = h0;
  *(uint32_t*)(g_Whi + base + i + 2) = h1;
  *(uint32_t*)(g_Wlo + base + i)     = l0;
  *(uint32_t*)(g_Wlo + base + i + 2) = l1;
}

// ---------------- LayerNorm -> fp16 hi (optionally fp32 g_Fx) --------------
// ln3 variant: blockIdx.y selects (x,g,b) -> slot y
__global__ __launch_bounds__(256)
void ln3_kernel(const float* __restrict__ x0, const float* __restrict__ g0,
                const float* __restrict__ b0, const float* __restrict__ x1,
                const float* __restrict__ g1, const float* __restrict__ b1,
                const float* __restrict__ x2, const float* __restrict__ g2,
                const float* __restrict__ b2) {
  __shared__ float sh[8];
  const int y = blockIdx.y;
  const float* x = y == 0 ? x0 : y == 1 ? x1 : x2;
  const float* g = y == 0 ? g0 : y == 1 ? g1 : g2;
  const float* b = y == 0 ? b0 : y == 1 ? b1 : b2;
  const int row = blockIdx.x, t = threadIdx.x;
  float4 v = ((const float4*)(x + (long)row * HIDN))[t];
  float mean = blockSum(v.x + v.y + v.z + v.w, sh) * (1.f / HIDN);
  float dx = v.x - mean, dy = v.y - mean, dz = v.z - mean, dw = v.w - mean;
  float var = blockSum(dx * dx + dy * dy + dz * dz + dw * dw, sh) * (1.f / HIDN);
  float rstd = rsqrtf(var + 1e-5f);
  float4 gv = ((const float4*)g)[t];
  float4 bv = ((const float4*)b)[t];
  const long off = (long)y * MSZ + (long)row * HIDN + t * 4;
  *(uint32_t*)(g_hi + off) =
      pack_h2(dx * rstd * gv.x + bv.x, dy * rstd * gv.y + bv.y);
  *(uint32_t*)(g_hi + off + 2) =
      pack_h2(dz * rstd * gv.z + bv.z, dw * rstd * gv.w + bv.w);
}

// fx = LN(g_X) -> g_Fx fp32 + slot3 fp16 hi
__global__ __launch_bounds__(256)
void ln_fx_kernel(const float* __restrict__ g, const float* __restrict__ b) {
  __shared__ float sh[8];
  const int row = blockIdx.x, t = threadIdx.x;
  float4 v = ((const float4*)(g_X + (long)row * HIDN))[t];
  float mean = blockSum(v.x + v.y + v.z + v.w, sh) * (1.f / HIDN);
  float dx = v.x - mean, dy = v.y - mean, dz = v.z - mean, dw = v.w - mean;
  float var = blockSum(dx * dx + dy * dy + dz * dz + dw * dw, sh) * (1.f / HIDN);
  float rstd = rsqrtf(var + 1e-5f);
  float4 gv = ((const float4*)g)[t];
  float4 bv = ((const float4*)b)[t];
  float4 o = make_float4(dx * rstd * gv.x + bv.x, dy * rstd * gv.y + bv.y,
                         dz * rstd * gv.z + bv.z, dw * rstd * gv.w + bv.w);
  ((float4*)(g_Fx + (long)row * HIDN))[t] = o;
  const long off = 3L * MSZ + (long)row * HIDN + t * 4;
  *(uint32_t*)(g_hi + off)     = pack_h2(o.x, o.y);
  *(uint32_t*)(g_hi + off + 2) = pack_h2(o.z, o.w);
}

// out = g_Fx + LN(g_Fo)*g3 + b3
__global__ __launch_bounds__(256)
void ln_add_kernel(const float* __restrict__ g, const float* __restrict__ b,
                   float* __restrict__ out) {
  __shared__ float sh[8];
  const int row = blockIdx.x, t = threadIdx.x;
  float4 v = ((const float4*)(g_Fo + (long)row * HIDN))[t];
  float mean = blockSum(v.x + v.y + v.z + v.w, sh) * (1.f / HIDN);
  float dx = v.x - mean, dy = v.y - mean, dz = v.z - mean, dw = v.w - mean;
  float var = blockSum(dx * dx + dy * dy + dz * dz + dw * dw, sh) * (1.f / HIDN);
  float rstd = rsqrtf(var + 1e-5f);
  float4 gv = ((const float4*)g)[t];
  float4 bv = ((const float4*)b)[t];
  float4 fx = ((const float4*)(g_Fx + (long)row * HIDN))[t];
  float4 o = make_float4(fx.x + dx * rstd * gv.x + bv.x,
                         fx.y + dy * rstd * gv.y + bv.y,
                         fx.z + dz * rstd * gv.z + bv.z,
                         fx.w + dw * rstd * gv.w + bv.w);
  ((float4*)(out + (long)row * HIDN))[t] = o;
}

// ---------------- fp16 2-term GEMM: C = A @ (Wh+Wl)^T + bias ---------------
__device__ __forceinline__ void gemm_load_stage(
    uint32_t sbase, const __half* Ah, const __half* Bh, const __half* Bl,
    int row0, int col0, int k0, int t) {
#pragma unroll
  for (int j = 0; j < 2; j++) {
    const int idx = t + j * 256;
    const int r = idx >> 2, cc = idx & 3;
    const uint32_t so = sbase + (uint32_t)(r * (LDT * 2) + cc * 16);
    const long ga = (long)(row0 + r) * HIDN + k0 + cc * 8;
    const long gb = (long)(col0 + r) * HIDN + k0 + cc * 8;
    cp16(so + OFF_A,   Ah + ga);
    cp16(so + OFF_BHI, Bh + gb);
    cp16(so + OFF_BLO, Bl + gb);
  }
}

__global__ __launch_bounds__(256, 2)
void gemm_mma(int aslot0, int cdst, int relu,
              const float* __restrict__ bias0, const float* __restrict__ bias1,
              const float* __restrict__ bias2) {
  extern __shared__ __align__(128) char smem[];
  const int z = blockIdx.z;
  const int slot = aslot0 + z;
  const __half* Ah = g_hi  + (long)slot * MSZ;
  const __half* Bh = g_Whi + (long)slot * WSZ;
  const __half* Bl = g_Wlo + (long)slot * WSZ;
  float* C = cdst ? g_Fo : (g_P + (long)z * MSZ);
  const float* bias = (z == 0) ? bias0 : ((z == 1) ? bias1 : bias2);

  const int t = threadIdx.x;
  const int wid = t >> 5, lane = t & 31;
  const int wm = wid >> 2, wn = wid & 3;
  const int row0 = blockIdx.y * BM, col0 = blockIdx.x * BN;
  const uint32_t sb = (uint32_t)__cvta_generic_to_shared(smem);

  float acc[4][4][4];
#pragma unroll
  for (int i = 0; i < 4; i++)
#pragma unroll
    for (int j = 0; j < 4; j++)
#pragma unroll
      for (int r = 0; r < 4; r++) acc[i][j][r] = 0.f;

  gemm_load_stage(sb, Ah, Bh, Bl, row0, col0, 0, t);
  CP_COMMIT();

  const uint32_t aOff = (uint32_t)((wm * 64 + (lane & 15)) * (LDT * 2) + (lane >> 4) * 16);
  const uint32_t bOff = (uint32_t)((wn * 32 + (lane & 15)) * (LDT * 2) + (lane >> 4) * 16);

  for (int s = 0; s < NS; s++) {
    if (s + 1 < NS) {
      gemm_load_stage(sb + (uint32_t)(((s + 1) & 1) * SSTRIDE),
                      Ah, Bh, Bl, row0, col0, (s + 1) * BK, t);
    }
    CP_COMMIT();
    CP_WAIT1();
    __syncthreads();
    const uint32_t st = sb + (uint32_t)((s & 1) * SSTRIDE);
#pragma unroll
    for (int kk = 0; kk < 2; kk++) {
      uint32_t ah[4][4];
#pragma unroll
      for (int mi = 0; mi < 4; mi++) {
        const uint32_t a = st + aOff + (uint32_t)(mi * 16 * (LDT * 2) + kk * 32);
        LDSM4(ah[mi], a + OFF_A);
      }
      uint32_t bh[2][4], bl[2][4];
#pragma unroll
      for (int bn = 0; bn < 2; bn++) {
        const uint32_t a = st + bOff + (uint32_t)(bn * 16 * (LDT * 2) + kk * 32);
        LDSM4(bh[bn], a + OFF_BHI);
        LDSM4(bl[bn], a + OFF_BLO);
      }
#pragma unroll
      for (int mi = 0; mi < 4; mi++) {
#pragma unroll
        for (int bn = 0; bn < 2; bn++) {
          const int ni = bn * 2;
          MMA(acc[mi][ni],     ah[mi], bh[bn][0], bh[bn][2]);
          MMA(acc[mi][ni],     ah[mi], bl[bn][0], bl[bn][2]);
          MMA(acc[mi][ni + 1], ah[mi], bh[bn][1], bh[bn][3]);
          MMA(acc[mi][ni + 1], ah[mi], bl[bn][1], bl[bn][3]);
        }
      }
    }
    __syncthreads();
  }

#pragma unroll
  for (int mi = 0; mi < 4; mi++) {
    const long r = row0 + wm * 64 + mi * 16 + (lane >> 2);
#pragma unroll
    for (int ni = 0; ni < 4; ni++) {
      const int c = col0 + wn * 32 + ni * 8 + (lane & 3) * 2;
      float2 bv = *(const float2*)(bias + c);
      float v0 = acc[mi][ni][0] + bv.x, v1 = acc[mi][ni][1] + bv.y;
      float v2 = acc[mi][ni][2] + bv.x, v3 = acc[mi][ni][3] + bv.y;
      if (relu) {
        v0 = fmaxf(v0, 0.f); v1 = fmaxf(v1, 0.f);
        v2 = fmaxf(v2, 0.f); v3 = fmaxf(v3, 0.f);
      }
      *(float2*)(C + r * HIDN + c)       = make_float2(v0, v1);
      *(float2*)(C + (r + 8) * HIDN + c) = make_float2(v2, v3);
    }
  }
}

// ---------------- RoPE + fp16 split: Q hi, K hi+lo, V hi -------------------
__global__ __launch_bounds__(512)
void rope_split_kernel() {
  const int row = blockIdx.x, y = blockIdx.y, t = threadIdx.x;
  const float* src = g_P + (long)y * MSZ + (long)row * HIDN;
  __half* dh = g_hi + (long)y * MSZ + (long)row * HIDN;
  __half* dl = g_lo + (long)y * MSZ + (long)row * HIDN;
  if (y < 2) {
    const int h = t >> 5, i = t & 31;
    const int s = row & (SEQ - 1);
    float inv = exp2f(-(float)i * (13.287712379549449f / 32.f));
    float ang = (float)s * inv;
    float sn, cs;
    sincosf(ang, &sn, &cs);
    const int e = h * HDIM + i;
    float x1 = src[e], x2 = src[e + 32];
    float o1 = x1 * cs - x2 * sn;
    float o2 = x2 * cs + x1 * sn;
    __half h1 = __float2half_rn(o1), h2 = __float2half_rn(o2);
    dh[e]      = h1;
    dh[e + 32] = h2;
    if (y == 1) {  // K needs lo residual
      dl[e]      = __float2half_rn(o1 - __half2float(h1));
      dl[e + 32] = __float2half_rn(o2 - __half2float(h2));
    }
  } else {
#pragma unroll
    for (int j = 0; j < 2; j++) {
      const int e = t + j * 512;
      dh[e] = __float2half_rn(src[e]);
    }
  }
}

// ---------------- fp16 tensor-core flash attention -------------------------
__device__ __forceinline__ void attn_load_kv(
    uint32_t sb, int st, const __half* Kh, const __half* Kl, const __half* Vh,
    const int* mask, char* smem, int b, int h, int k0, int t) {
#pragma unroll
  for (int j = 0; j < 4; j++) {
    const int idx = t + j * 128;
    const int r = idx >> 3, cc = idx & 7;
    const long off = (long)(b * SEQ + k0 + r) * HIDN + h * HDIM + cc * 8;
    const uint32_t so = sb + (uint32_t)(r * (ALD * 2) + cc * 16);
    cp16(so + SKH(st), Kh + off);
    cp16(so + SKL(st), Kl + off);
    cp16(so + SVH(st), Vh + off);
  }
  if (t < 64) ((int*)(smem + SMSK(st)))[t] = mask[b * SEQ + k0 + t];
}

__global__ __launch_bounds__(128, 3)
void attn_mma(const int* __restrict__ mask) {
  extern __shared__ __align__(128) char smem[];
  const uint32_t sb = (uint32_t)__cvta_generic_to_shared(smem);
  const int t = threadIdx.x, lane = t & 31, wid = t >> 5;
  const int b = blockIdx.z, h = blockIdx.y, q0 = blockIdx.x * 64;
  const int m0 = wid * 16;
  const __half* Qh = g_hi;
  const __half* Kh = g_hi + MSZ;
  const __half* Kl = g_lo + MSZ;
  const __half* Vh = g_hi + 2L * MSZ;

#pragma unroll
  for (int j = 0; j < 4; j++) {
    const int idx = t + j * 128;
    const int r = idx >> 3, cc = idx & 7;
    const long off = (long)(b * SEQ + q0 + r) * HIDN + h * HDIM + cc * 8;
    cp16(sb + (uint32_t)(r * (ALD * 2) + cc * 16) + SQH, Qh + off);
  }
  attn_load_kv(sb, 0, Kh, Kl, Vh, mask, smem, b, h, 0, t);
  CP_COMMIT();
  CP_WAIT0();
  __syncthreads();

  uint32_t qh[4][4];
  {
    const uint32_t base =
        sb + (uint32_t)((m0 + (lane & 15)) * (ALD * 2) + (lane >> 4) * 16);
#pragma unroll
    for (int kc = 0; kc < 4; kc++) LDSM4(qh[kc], base + SQH + kc * 32);
  }

  float o[8][4];
#pragma unroll
  for (int i = 0; i < 8; i++)
#pragma unroll
    for (int j = 0; j < 4; j++) o[i][j] = 0.f;
  float mA = -1e30f, mB = -1e30f, lA = 0.f, lB = 0.f;

  for (int kb = 0; kb < SEQ / 64; kb++) {
    const int st = kb & 1;
    if (kb + 1 < SEQ / 64) {
      attn_load_kv(sb, st ^ 1, Kh, Kl, Vh, mask, smem, b, h, (kb + 1) * 64, t);
    }
    CP_COMMIT();
    CP_WAIT1();
    __syncthreads();

    // S = qh (kh + kl)^T, fp32 accum
    float s[8][4];
#pragma unroll
    for (int i = 0; i < 8; i++)
#pragma unroll
      for (int j = 0; j < 4; j++) s[i][j] = 0.f;
#pragma unroll
    for (int kc = 0; kc < 4; kc++) {
      const uint32_t base =
          sb + (uint32_t)((lane & 15) * (ALD * 2) + (lane >> 4) * 16 + kc * 32);
#pragma unroll
      for (int np = 0; np < 4; np++) {
        uint32_t kh4[4], kl4[4];
        const uint32_t a = base + (uint32_t)(np * 16 * (ALD * 2));
        LDSM4(kh4, a + SKH(st));
        LDSM4(kl4, a + SKL(st));
        MMA(s[2 * np],     qh[kc], kh4[0], kh4[2]);
        MMA(s[2 * np],     qh[kc], kl4[0], kl4[2]);
        MMA(s[2 * np + 1], qh[kc], kh4[1], kh4[3]);
        MMA(s[2 * np + 1], qh[kc], kl4[1], kl4[3]);
      }
    }

    // scale + mask (reference: scores/8 then masked -> 1e-10)
    const int cbase = (lane & 3) * 2;
    const int* smk = (const int*)(smem + SMSK(st));
#pragma unroll
    for (int nt = 0; nt < 8; nt++) {
      const int c = nt * 8 + cbase;
      const int mk0 = smk[c], mk1 = smk[c + 1];
      s[nt][0] = mk0 ? s[nt][0] * 0.125f : 1e-10f;
      s[nt][2] = mk0 ? s[nt][2] * 0.125f : 1e-10f;
      s[nt][1] = mk1 ? s[nt][1] * 0.125f : 1e-10f;
      s[nt][3] = mk1 ? s[nt][3] * 0.125f : 1e-10f;
    }

    // online softmax
    float bmA = -1e30f, bmB = -1e30f;
#pragma unroll
    for (int nt = 0; nt < 8; nt++) {
      bmA = fmaxf(bmA, fmaxf(s[nt][0], s[nt][1]));
      bmB = fmaxf(bmB, fmaxf(s[nt][2], s[nt][3]));
    }
#pragma unroll
    for (int off = 1; off <= 2; off <<= 1) {
      bmA = fmaxf(bmA, __shfl_xor_sync(0xffffffffu, bmA, off));
      bmB = fmaxf(bmB, __shfl_xor_sync(0xffffffffu, bmB, off));
    }
    const float mnA = fmaxf(mA, bmA), mnB = fmaxf(mB, bmB);
    const float cA = __expf(mA - mnA), cB = __expf(mB - mnB);
    mA = mnA; mB = mnB;
    float p[8][4];
    float sA = 0.f, sB = 0.f;
#pragma unroll
    for (int nt = 0; nt < 8; nt++) {
      p[nt][0] = __expf(s[nt][0] - mnA);
      p[nt][1] = __expf(s[nt][1] - mnA);
      p[nt][2] = __expf(s[nt][2] - mnB);
      p[nt][3] = __expf(s[nt][3] - mnB);
      sA += p[nt][0] + p[nt][1];
      sB += p[nt][2] + p[nt][3];
    }
#pragma unroll
    for (int off = 1; off <= 2; off <<= 1) {
      sA += __shfl_xor_sync(0xffffffffu, sA, off);
      sB += __shfl_xor_sync(0xffffffffu, sB, off);
    }
    lA = lA * cA + sA;
    lB = lB * cB + sB;
#pragma unroll
    for (int nt = 0; nt < 8; nt++) {
      o[nt][0] *= cA; o[nt][1] *= cA;
      o[nt][2] *= cB; o[nt][3] *= cB;
    }

    // pack P into A-frags (fp16 hi/lo; lossless to ~2^-22)
    uint32_t ph[4][4], pl[4][4];
#pragma unroll
    for (int kc = 0; kc < 4; kc++) {
      split2h(p[2 * kc][0],     p[2 * kc][1],     ph[kc][0], pl[kc][0]);
      split2h(p[2 * kc][2],     p[2 * kc][3],     ph[kc][1], pl[kc][1]);
      split2h(p[2 * kc + 1][0], p[2 * kc + 1][1], ph[kc][2], pl[kc][2]);
      split2h(p[2 * kc + 1][2], p[2 * kc + 1][3], ph[kc][3], pl[kc][3]);
    }

    // O += (ph + pl) vh
#pragma unroll
    for (int kc = 0; kc < 4; kc++) {
      const uint32_t vbase =
          sb + (uint32_t)((kc * 16 + (lane & 15)) * (ALD * 2) + (lane >> 4) * 16);
#pragma unroll
      for (int np = 0; np < 4; np++) {
        uint32_t vh4[4];
        LDSM4T(vh4, vbase + (uint32_t)(np * 32) + SVH(st));
        MMA(o[2 * np],     ph[kc], vh4[0], vh4[1]);
        MMA(o[2 * np],     pl[kc], vh4[0], vh4[1]);
        MMA(o[2 * np + 1], ph[kc], vh4[2], vh4[3]);
        MMA(o[2 * np + 1], pl[kc], vh4[2], vh4[3]);
      }
    }
    __syncthreads();
  }

  // epilogue
  const float iA = 1.f / lA, iB = 1.f / lB;
  const long rA = (long)(b * SEQ + q0 + m0 + (lane >> 2));
  const long rB = rA + 8;
#pragma unroll
  for (int nt = 0; nt < 8; nt++) {
    const int col = h * HDIM + nt * 8 + (lane & 3) * 2;
    *(float2*)(g_X + rA * HIDN + col) = make_float2(o[nt][0] * iA, o[nt][1] * iA);
    *(float2*)(g_X + rB * HIDN + col) = make_float2(o[nt][2] * iB, o[nt][3] * iB);
  }
}

// ---------------- launch -----------------------------------------------------
extern "C" void kernel_launch(void* const* d_in, const int* in_sizes, int n_in,
                              void* d_out, int out_size) {
  const float* q   = (const float*)d_in[0];
  const float* k   = (const float*)d_in[1];
  const float* v   = (const float*)d_in[2];
  const float* g1q = (const float*)d_in[3];
  const float* b1q = (const float*)d_in[4];
  const float* g1k = (const float*)d_in[5];
  const float* b1k = (const float*)d_in[6];
  const float* g1v = (const float*)d_in[7];
  const float* b1v = (const float*)d_in[8];
  const float* Wq  = (const float*)d_in[9];
  const float* bq  = (const float*)d_in[10];
  const float* Wk  = (const float*)d_in[11];
  const float* bk  = (const float*)d_in[12];
  const float* Wv  = (const float*)d_in[13];
  const float* bv  = (const float*)d_in[14];
  const float* g2  = (const float*)d_in[15];
  const float* b2  = (const float*)d_in[16];
  const float* g3  = (const float*)d_in[17];
  const float* b3  = (const float*)d_in[18];
  const float* Wf  = (const float*)d_in[19];
  const float* bf  = (const float*)d_in[20];
  const int*  mask = (const int*)d_in[21];
  float* out = (float*)d_out;

  cudaFuncSetAttribute(gemm_mma, cudaFuncAttributeMaxDynamicSharedMemorySize, GEMM_SMEM);
  cudaFuncSetAttribute(attn_mma, cudaFuncAttributeMaxDynamicSharedMemorySize, ATTN_SMEM);

  // 0) weight split (hi/lo fp16)
  wconv_kernel<<<dim3(WSZ / 1024, 4), 256>>>(Wq, Wk, Wv, Wf);

  // 1) LayerNorms of q,k,v -> fp16 hi slots 0..2 (one launch)
  ln3_kernel<<<dim3(MROWS, 3), 256>>>(q, g1q, b1q, k, g1k, b1k, v, g1v, b1v);

  // 2) Q/K/V projections (fused z=0..2) -> g_P fp32
  gemm_mma<<<dim3(HIDN / BN, MROWS / BM, 3), 256, GEMM_SMEM>>>(0, 0, 0, bq, bk, bv);

  // 3) RoPE + split: Q hi, K hi+lo, V hi
  rope_split_kernel<<<dim3(MROWS, 3), 512>>>();

  // 4) fp16 tensor-core flash attention -> g_X
  attn_mma<<<dim3(SEQ / 64, NHEAD, 4), 128, ATTN_SMEM>>>(mask);

  // 5) fx = LN(x) -> g_Fx fp32 + slot 3 fp16 hi
  ln_fx_kernel<<<MROWS, 256>>>(g2, b2);

  // 6) fo = relu(fx @ Wf^T + bf)
  gemm_mma<<<dim3(HIDN / BN, MROWS / BM, 1), 256, GEMM_SMEM>>>(3, 1, 1, bf, bf, bf);

  // 7) out = fx + LN(fo)
  ln_add_kernel<<<MROWS, 256>>>(g3, b3, out);
}

// round 8
// speedup vs baseline: 3.0004x; 1.0044x over previous
#include <cuda_runtime.h>
#include <cuda_fp16.h>
#include <math.h>
#include <stdint.h>

#define HIDN 1024
#define MROWS 4096
#define SEQ 1024
#define NHEAD 16
#define HDIM 64
#define MSZ (MROWS * HIDN)
#define WSZ (HIDN * HIDN)

// mma.sync GEMM tiling (fp16 2-term: A hi-only, B hi+lo)
#define BM 128
#define BN 128
#define BK 32
#define NS (HIDN / BK)                 // 32 k-stages
#define LDT 40                         // row stride in fp16 elems (32 + 8 pad)
#define TBYTES (128 * LDT * 2)         // 10240 bytes per tile
#define OFF_A 0
#define OFF_BHI (1 * TBYTES)
#define OFF_BLO (2 * TBYTES)
#define SSTRIDE (3 * TBYTES)           // 30720 per stage
#define GEMM_SMEM (2 * SSTRIDE)        // 61440, 2-stage

// attention tiling (Q hi, K hi+lo, V hi; double-buffered K/V)
#define ALD 72                         // 64 + 8 pad fp16 elems per row
#define ATILE_B (64 * ALD * 2)         // 9216 bytes per 64x64 tile
#define SQH 0
#define SKH(st) (ATILE_B * (1 + (st) * 3))
#define SKL(st) (SKH(st) + ATILE_B)
#define SVH(st) (SKH(st) + 2 * ATILE_B)
#define SMSK(st) (7 * ATILE_B + (st) * 256)
#define ATTN_SMEM (7 * ATILE_B + 512)  // 65024 => 3 CTAs/SM

// ---------------- scratch (device globals; no allocation allowed) ----------
__device__ __align__(16) __half g_hi[4L * MSZ];   // hi activations (0=Q,1=K,2=V,3=Fx)
__device__ __align__(16) __half g_lo[4L * MSZ];   // lo residuals (only K slot used)
__device__ __align__(16) __half g_Whi[4L * WSZ];  // weights hi (0=Wq,1=Wk,2=Wv,3=Wf)
__device__ __align__(16) __half g_Wlo[4L * WSZ];  // weights lo
__device__ __align__(16) float g_P [3L * MSZ];  // Q,K,V projections fp32
__device__ __align__(16) float g_X [MSZ];       // attention output
__device__ __align__(16) float g_Fx[MSZ];       // LN2 output (residual)
__device__ __align__(16) float g_Fo[MSZ];       // relu(ffn)

// ---------------- PTX helpers ----------------
__device__ __forceinline__ void cp16(uint32_t dst, const void* src) {
  asm volatile("cp.async.cg.shared.global [%0], [%1], 16;\n"
               :: "r"(dst), "l"(__cvta_generic_to_global(src)) : "memory");
}
#define CP_COMMIT() asm volatile("cp.async.commit_group;" ::: "memory")
#define CP_WAIT1()  asm volatile("cp.async.wait_group 1;" ::: "memory")
#define CP_WAIT0()  asm volatile("cp.async.wait_group 0;" ::: "memory")

#define LDSM4(r, addr) asm volatile( \
  "ldmatrix.sync.aligned.m8n8.x4.shared.b16 {%0,%1,%2,%3}, [%4];" \
  : "=r"((r)[0]), "=r"((r)[1]), "=r"((r)[2]), "=r"((r)[3]) : "r"(addr))

#define LDSM4T(r, addr) asm volatile( \
  "ldmatrix.sync.aligned.m8n8.x4.trans.shared.b16 {%0,%1,%2,%3}, [%4];" \
  : "=r"((r)[0]), "=r"((r)[1]), "=r"((r)[2]), "=r"((r)[3]) : "r"(addr))

#define MMA(acc, a, b0, b1) asm volatile( \
  "mma.sync.aligned.m16n8k16.row.col.f32.f16.f16.f32 " \
  "{%0,%1,%2,%3}, {%4,%5,%6,%7}, {%8,%9}, {%0,%1,%2,%3};" \
  : "+f"((acc)[0]), "+f"((acc)[1]), "+f"((acc)[2]), "+f"((acc)[3]) \
  : "r"((a)[0]), "r"((a)[1]), "r"((a)[2]), "r"((a)[3]), "r"(b0), "r"(b1))

__device__ __forceinline__ uint32_t pack_h2(float a, float b) {
  __half2 h(__float2half_rn(a), __float2half_rn(b));
  return *(uint32_t*)&h;
}
__device__ __forceinline__ void split2h(float a, float b, uint32_t& hi, uint32_t& lo) {
  __half ha = __float2half_rn(a), hb = __float2half_rn(b);
  __half2 h(ha, hb);
  __half2 l(__float2half_rn(a - __half2float(ha)),
            __float2half_rn(b - __half2float(hb)));
  hi = *(uint32_t*)&h;
  lo = *(uint32_t*)&l;
}

// ---------------- reductions ----------------
__device__ __forceinline__ float warpSum(float v) {
#pragma unroll
  for (int o = 16; o; o >>= 1) v += __shfl_xor_sync(0xffffffffu, v, o);
  return v;
}
__device__ __forceinline__ float blockSum(float partial, float* sh) {
  __syncthreads();
  float w = warpSum(partial);
  if ((threadIdx.x & 31) == 0) sh[threadIdx.x >> 5] = w;
  __syncthreads();
  float tot = 0.f;
#pragma unroll
  for (int i = 0; i < 8; i++) tot += sh[i];
  return tot;
}

// ---------------- weight split: fp32 -> fp16 hi/lo -------------------------
__global__ __launch_bounds__(256)
void wconv_kernel(const float* __restrict__ w0, const float* __restrict__ w1,
                  const float* __restrict__ w2, const float* __restrict__ w3) {
  const float* src = blockIdx.y == 0 ? w0 : blockIdx.y == 1 ? w1
                   : blockIdx.y == 2 ? w2 : w3;
  const long base = (long)blockIdx.y * WSZ;
  const long i = ((long)blockIdx.x * 256 + threadIdx.x) * 4;
  float4 v = *(const float4*)(src + i);
  uint32_t h0, l0, h1, l1;
  split2h(v.x, v.y, h0, l0);
  split2h(v.z, v.w, h1, l1);
  *(uint32_t*)(g_Whi + base + i)     = h0;
  *(uint32_t*)(g_Whi + base + i + 2) = h1;
  *(uint32_t*)(g_Wlo + base + i)     = l0;
  *(uint32_t*)(g_Wlo + base + i + 2) = l1;
}

// ---------------- LayerNorm -> fp16 hi (optionally fp32 g_Fx) --------------
// ln3 variant: blockIdx.y selects (x,g,b) -> slot y
__global__ __launch_bounds__(256)
void ln3_kernel(const float* __restrict__ x0, const float* __restrict__ g0,
                const float* __restrict__ b0, const float* __restrict__ x1,
                const float* __restrict__ g1, const float* __restrict__ b1,
                const float* __restrict__ x2, const float* __restrict__ g2,
                const float* __restrict__ b2) {
  __shared__ float sh[8];
  const int y = blockIdx.y;
  const float* x = y == 0 ? x0 : y == 1 ? x1 : x2;
  const float* g = y == 0 ? g0 : y == 1 ? g1 : g2;
  const float* b = y == 0 ? b0 : y == 1 ? b1 : b2;
  const int row = blockIdx.x, t = threadIdx.x;
  float4 v = ((const float4*)(x + (long)row * HIDN))[t];
  float mean = blockSum(v.x + v.y + v.z + v.w, sh) * (1.f / HIDN);
  float dx = v.x - mean, dy = v.y - mean, dz = v.z - mean, dw = v.w - mean;
  float var = blockSum(dx * dx + dy * dy + dz * dz + dw * dw, sh) * (1.f / HIDN);
  float rstd = rsqrtf(var + 1e-5f);
  float4 gv = ((const float4*)g)[t];
  float4 bv = ((const float4*)b)[t];
  const long off = (long)y * MSZ + (long)row * HIDN + t * 4;
  *(uint32_t*)(g_hi + off) =
      pack_h2(dx * rstd * gv.x + bv.x, dy * rstd * gv.y + bv.y);
  *(uint32_t*)(g_hi + off + 2) =
      pack_h2(dz * rstd * gv.z + bv.z, dw * rstd * gv.w + bv.w);
}

// fx = LN(g_X) -> g_Fx fp32 + slot3 fp16 hi
__global__ __launch_bounds__(256)
void ln_fx_kernel(const float* __restrict__ g, const float* __restrict__ b) {
  __shared__ float sh[8];
  const int row = blockIdx.x, t = threadIdx.x;
  float4 v = ((const float4*)(g_X + (long)row * HIDN))[t];
  float mean = blockSum(v.x + v.y + v.z + v.w, sh) * (1.f / HIDN);
  float dx = v.x - mean, dy = v.y - mean, dz = v.z - mean, dw = v.w - mean;
  float var = blockSum(dx * dx + dy * dy + dz * dz + dw * dw, sh) * (1.f / HIDN);
  float rstd = rsqrtf(var + 1e-5f);
  float4 gv = ((const float4*)g)[t];
  float4 bv = ((const float4*)b)[t];
  float4 o = make_float4(dx * rstd * gv.x + bv.x, dy * rstd * gv.y + bv.y,
                         dz * rstd * gv.z + bv.z, dw * rstd * gv.w + bv.w);
  ((float4*)(g_Fx + (long)row * HIDN))[t] = o;
  const long off = 3L * MSZ + (long)row * HIDN + t * 4;
  *(uint32_t*)(g_hi + off)     = pack_h2(o.x, o.y);
  *(uint32_t*)(g_hi + off + 2) = pack_h2(o.z, o.w);
}

// out = g_Fx + LN(g_Fo)*g3 + b3
__global__ __launch_bounds__(256)
void ln_add_kernel(const float* __restrict__ g, const float* __restrict__ b,
                   float* __restrict__ out) {
  __shared__ float sh[8];
  const int row = blockIdx.x, t = threadIdx.x;
  float4 v = ((const float4*)(g_Fo + (long)row * HIDN))[t];
  float mean = blockSum(v.x + v.y + v.z + v.w, sh) * (1.f / HIDN);
  float dx = v.x - mean, dy = v.y - mean, dz = v.z - mean, dw = v.w - mean;
  float var = blockSum(dx * dx + dy * dy + dz * dz + dw * dw, sh) * (1.f / HIDN);
  float rstd = rsqrtf(var + 1e-5f);
  float4 gv = ((const float4*)g)[t];
  float4 bv = ((const float4*)b)[t];
  float4 fx = ((const float4*)(g_Fx + (long)row * HIDN))[t];
  float4 o = make_float4(fx.x + dx * rstd * gv.x + bv.x,
                         fx.y + dy * rstd * gv.y + bv.y,
                         fx.z + dz * rstd * gv.z + bv.z,
                         fx.w + dw * rstd * gv.w + bv.w);
  ((float4*)(out + (long)row * HIDN))[t] = o;
}

// ---------------- fp16 2-term GEMM: C = A @ (Wh+Wl)^T + bias ---------------
__device__ __forceinline__ void gemm_load_stage(
    uint32_t sbase, const __half* Ah, const __half* Bh, const __half* Bl,
    int row0, int col0, int k0, int t) {
#pragma unroll
  for (int j = 0; j < 2; j++) {
    const int idx = t + j * 256;
    const int r = idx >> 2, cc = idx & 3;
    const uint32_t so = sbase + (uint32_t)(r * (LDT * 2) + cc * 16);
    const long ga = (long)(row0 + r) * HIDN + k0 + cc * 8;
    const long gb = (long)(col0 + r) * HIDN + k0 + cc * 8;
    cp16(so + OFF_A,   Ah + ga);
    cp16(so + OFF_BHI, Bh + gb);
    cp16(so + OFF_BLO, Bl + gb);
  }
}

__global__ __launch_bounds__(256, 2)
void gemm_mma(int aslot0, int cdst, int relu,
              const float* __restrict__ bias0, const float* __restrict__ bias1,
              const float* __restrict__ bias2) {
  extern __shared__ __align__(128) char smem[];
  const int z = blockIdx.z;
  const int slot = aslot0 + z;
  const __half* Ah = g_hi  + (long)slot * MSZ;
  const __half* Bh = g_Whi + (long)slot * WSZ;
  const __half* Bl = g_Wlo + (long)slot * WSZ;
  float* C = cdst ? g_Fo : (g_P + (long)z * MSZ);
  const float* bias = (z == 0) ? bias0 : ((z == 1) ? bias1 : bias2);

  const int t = threadIdx.x;
  const int wid = t >> 5, lane = t & 31;
  const int wm = wid >> 2, wn = wid & 3;
  const int row0 = blockIdx.y * BM, col0 = blockIdx.x * BN;
  const uint32_t sb = (uint32_t)__cvta_generic_to_shared(smem);

  float acc[4][4][4];
#pragma unroll
  for (int i = 0; i < 4; i++)
#pragma unroll
    for (int j = 0; j < 4; j++)
#pragma unroll
      for (int r = 0; r < 4; r++) acc[i][j][r] = 0.f;

  gemm_load_stage(sb, Ah, Bh, Bl, row0, col0, 0, t);
  CP_COMMIT();

  const uint32_t aOff = (uint32_t)((wm * 64 + (lane & 15)) * (LDT * 2) + (lane >> 4) * 16);
  const uint32_t bOff = (uint32_t)((wn * 32 + (lane & 15)) * (LDT * 2) + (lane >> 4) * 16);

  for (int s = 0; s < NS; s++) {
    if (s + 1 < NS) {
      gemm_load_stage(sb + (uint32_t)(((s + 1) & 1) * SSTRIDE),
                      Ah, Bh, Bl, row0, col0, (s + 1) * BK, t);
    }
    CP_COMMIT();
    CP_WAIT1();
    __syncthreads();
    const uint32_t st = sb + (uint32_t)((s & 1) * SSTRIDE);
#pragma unroll
    for (int kk = 0; kk < 2; kk++) {
      uint32_t ah[4][4];
#pragma unroll
      for (int mi = 0; mi < 4; mi++) {
        const uint32_t a = st + aOff + (uint32_t)(mi * 16 * (LDT * 2) + kk * 32);
        LDSM4(ah[mi], a + OFF_A);
      }
      uint32_t bh[2][4], bl[2][4];
#pragma unroll
      for (int bn = 0; bn < 2; bn++) {
        const uint32_t a = st + bOff + (uint32_t)(bn * 16 * (LDT * 2) + kk * 32);
        LDSM4(bh[bn], a + OFF_BHI);
        LDSM4(bl[bn], a + OFF_BLO);
      }
#pragma unroll
      for (int mi = 0; mi < 4; mi++) {
#pragma unroll
        for (int bn = 0; bn < 2; bn++) {
          const int ni = bn * 2;
          MMA(acc[mi][ni],     ah[mi], bh[bn][0], bh[bn][2]);
          MMA(acc[mi][ni],     ah[mi], bl[bn][0], bl[bn][2]);
          MMA(acc[mi][ni + 1], ah[mi], bh[bn][1], bh[bn][3]);
          MMA(acc[mi][ni + 1], ah[mi], bl[bn][1], bl[bn][3]);
        }
      }
    }
    __syncthreads();
  }

#pragma unroll
  for (int mi = 0; mi < 4; mi++) {
    const long r = row0 + wm * 64 + mi * 16 + (lane >> 2);
#pragma unroll
    for (int ni = 0; ni < 4; ni++) {
      const int c = col0 + wn * 32 + ni * 8 + (lane & 3) * 2;
      float2 bv = *(const float2*)(bias + c);
      float v0 = acc[mi][ni][0] + bv.x, v1 = acc[mi][ni][1] + bv.y;
      float v2 = acc[mi][ni][2] + bv.x, v3 = acc[mi][ni][3] + bv.y;
      if (relu) {
        v0 = fmaxf(v0, 0.f); v1 = fmaxf(v1, 0.f);
        v2 = fmaxf(v2, 0.f); v3 = fmaxf(v3, 0.f);
      }
      *(float2*)(C + r * HIDN + c)       = make_float2(v0, v1);
      *(float2*)(C + (r + 8) * HIDN + c) = make_float2(v2, v3);
    }
  }
}

// ---------------- RoPE + fp16 split: Q hi, K hi+lo, V hi -------------------
__global__ __launch_bounds__(512)
void rope_split_kernel() {
  const int row = blockIdx.x, y = blockIdx.y, t = threadIdx.x;
  const float* src = g_P + (long)y * MSZ + (long)row * HIDN;
  __half* dh = g_hi + (long)y * MSZ + (long)row * HIDN;
  __half* dl = g_lo + (long)y * MSZ + (long)row * HIDN;
  if (y < 2) {
    const int h = t >> 5, i = t & 31;
    const int s = row & (SEQ - 1);
    float inv = exp2f(-(float)i * (13.287712379549449f / 32.f));
    float ang = (float)s * inv;
    float sn, cs;
    sincosf(ang, &sn, &cs);
    const int e = h * HDIM + i;
    float x1 = src[e], x2 = src[e + 32];
    float o1 = x1 * cs - x2 * sn;
    float o2 = x2 * cs + x1 * sn;
    __half h1 = __float2half_rn(o1), h2 = __float2half_rn(o2);
    dh[e]      = h1;
    dh[e + 32] = h2;
    if (y == 1) {  // K needs lo residual
      dl[e]      = __float2half_rn(o1 - __half2float(h1));
      dl[e + 32] = __float2half_rn(o2 - __half2float(h2));
    }
  } else {
#pragma unroll
    for (int j = 0; j < 2; j++) {
      const int e = t + j * 512;
      dh[e] = __float2half_rn(src[e]);
    }
  }
}

// ---------------- fp16 tensor-core flash attention -------------------------
__device__ __forceinline__ void attn_load_kv(
    uint32_t sb, int st, const __half* Kh, const __half* Kl, const __half* Vh,
    const int* mask, char* smem, int b, int h, int k0, int t) {
#pragma unroll
  for (int j = 0; j < 4; j++) {
    const int idx = t + j * 128;
    const int r = idx >> 3, cc = idx & 7;
    const long off = (long)(b * SEQ + k0 + r) * HIDN + h * HDIM + cc * 8;
    const uint32_t so = sb + (uint32_t)(r * (ALD * 2) + cc * 16);
    cp16(so + SKH(st), Kh + off);
    cp16(so + SKL(st), Kl + off);
    cp16(so + SVH(st), Vh + off);
  }
  if (t < 64) ((int*)(smem + SMSK(st)))[t] = mask[b * SEQ + k0 + t];
}

__global__ __launch_bounds__(128, 3)
void attn_mma(const int* __restrict__ mask) {
  extern __shared__ __align__(128) char smem[];
  const uint32_t sb = (uint32_t)__cvta_generic_to_shared(smem);
  const int t = threadIdx.x, lane = t & 31, wid = t >> 5;
  const int b = blockIdx.z, h = blockIdx.y, q0 = blockIdx.x * 64;
  const int m0 = wid * 16;
  const __half* Qh = g_hi;
  const __half* Kh = g_hi + MSZ;
  const __half* Kl = g_lo + MSZ;
  const __half* Vh = g_hi + 2L * MSZ;

#pragma unroll
  for (int j = 0; j < 4; j++) {
    const int idx = t + j * 128;
    const int r = idx >> 3, cc = idx & 7;
    const long off = (long)(b * SEQ + q0 + r) * HIDN + h * HDIM + cc * 8;
    cp16(sb + (uint32_t)(r * (ALD * 2) + cc * 16) + SQH, Qh + off);
  }
  attn_load_kv(sb, 0, Kh, Kl, Vh, mask, smem, b, h, 0, t);
  CP_COMMIT();
  CP_WAIT0();
  __syncthreads();

  uint32_t qh[4][4];
  {
    const uint32_t base =
        sb + (uint32_t)((m0 + (lane & 15)) * (ALD * 2) + (lane >> 4) * 16);
#pragma unroll
    for (int kc = 0; kc < 4; kc++) LDSM4(qh[kc], base + SQH + kc * 32);
  }

  float o[8][4];
#pragma unroll
  for (int i = 0; i < 8; i++)
#pragma unroll
    for (int j = 0; j < 4; j++) o[i][j] = 0.f;
  float mA = -1e30f, mB = -1e30f, lA = 0.f, lB = 0.f;

  for (int kb = 0; kb < SEQ / 64; kb++) {
    const int st = kb & 1;
    if (kb + 1 < SEQ / 64) {
      attn_load_kv(sb, st ^ 1, Kh, Kl, Vh, mask, smem, b, h, (kb + 1) * 64, t);
    }
    CP_COMMIT();
    CP_WAIT1();
    __syncthreads();

    // S = qh (kh + kl)^T, fp32 accum
    float s[8][4];
#pragma unroll
    for (int i = 0; i < 8; i++)
#pragma unroll
      for (int j = 0; j < 4; j++) s[i][j] = 0.f;
#pragma unroll
    for (int kc = 0; kc < 4; kc++) {
      const uint32_t base =
          sb + (uint32_t)((lane & 15) * (ALD * 2) + (lane >> 4) * 16 + kc * 32);
#pragma unroll
      for (int np = 0; np < 4; np++) {
        uint32_t kh4[4], kl4[4];
        const uint32_t a = base + (uint32_t)(np * 16 * (ALD * 2));
        LDSM4(kh4, a + SKH(st));
        LDSM4(kl4, a + SKL(st));
        MMA(s[2 * np],     qh[kc], kh4[0], kh4[2]);
        MMA(s[2 * np],     qh[kc], kl4[0], kl4[2]);
        MMA(s[2 * np + 1], qh[kc], kh4[1], kh4[3]);
        MMA(s[2 * np + 1], qh[kc], kl4[1], kl4[3]);
      }
    }

    // scale + mask (reference: scores/8 then masked -> 1e-10)
    const int cbase = (lane & 3) * 2;
    const int* smk = (const int*)(smem + SMSK(st));
#pragma unroll
    for (int nt = 0; nt < 8; nt++) {
      const int c = nt * 8 + cbase;
      const int mk0 = smk[c], mk1 = smk[c + 1];
      s[nt][0] = mk0 ? s[nt][0] * 0.125f : 1e-10f;
      s[nt][2] = mk0 ? s[nt][2] * 0.125f : 1e-10f;
      s[nt][1] = mk1 ? s[nt][1] * 0.125f : 1e-10f;
      s[nt][3] = mk1 ? s[nt][3] * 0.125f : 1e-10f;
    }

    // online softmax
    float bmA = -1e30f, bmB = -1e30f;
#pragma unroll
    for (int nt = 0; nt < 8; nt++) {
      bmA = fmaxf(bmA, fmaxf(s[nt][0], s[nt][1]));
      bmB = fmaxf(bmB, fmaxf(s[nt][2], s[nt][3]));
    }
#pragma unroll
    for (int off = 1; off <= 2; off <<= 1) {
      bmA = fmaxf(bmA, __shfl_xor_sync(0xffffffffu, bmA, off));
      bmB = fmaxf(bmB, __shfl_xor_sync(0xffffffffu, bmB, off));
    }
    const float mnA = fmaxf(mA, bmA), mnB = fmaxf(mB, bmB);
    const float cA = __expf(mA - mnA), cB = __expf(mB - mnB);
    mA = mnA; mB = mnB;
    float p[8][4];
    float sA = 0.f, sB = 0.f;
#pragma unroll
    for (int nt = 0; nt < 8; nt++) {
      p[nt][0] = __expf(s[nt][0] - mnA);
      p[nt][1] = __expf(s[nt][1] - mnA);
      p[nt][2] = __expf(s[nt][2] - mnB);
      p[nt][3] = __expf(s[nt][3] - mnB);
      sA += p[nt][0] + p[nt][1];
      sB += p[nt][2] + p[nt][3];
    }
#pragma unroll
    for (int off = 1; off <= 2; off <<= 1) {
      sA += __shfl_xor_sync(0xffffffffu, sA, off);
      sB += __shfl_xor_sync(0xffffffffu, sB, off);
    }
    lA = lA * cA + sA;
    lB = lB * cB + sB;
#pragma unroll
    for (int nt = 0; nt < 8; nt++) {
      o[nt][0] *= cA; o[nt][1] *= cA;
      o[nt][2] *= cB; o[nt][3] *= cB;
    }

    // pack P into A-frags (fp16 hi/lo; lossless to ~2^-22)
    uint32_t ph[4][4], pl[4][4];
#pragma unroll
    for (int kc = 0; kc < 4; kc++) {
      split2h(p[2 * kc][0],     p[2 * kc][1],     ph[kc][0], pl[kc][0]);
      split2h(p[2 * kc][2],     p[2 * kc][3],     ph[kc][1], pl[kc][1]);
      split2h(p[2 * kc + 1][0], p[2 * kc + 1][1], ph[kc][2], pl[kc][2]);
      split2h(p[2 * kc + 1][2], p[2 * kc + 1][3], ph[kc][3], pl[kc][3]);
    }

    // O += (ph + pl) vh
#pragma unroll
    for (int kc = 0; kc < 4; kc++) {
      const uint32_t vbase =
          sb + (uint32_t)((kc * 16 + (lane & 15)) * (ALD * 2) + (lane >> 4) * 16);
#pragma unroll
      for (int np = 0; np < 4; np++) {
        uint32_t vh4[4];
        LDSM4T(vh4, vbase + (uint32_t)(np * 32) + SVH(st));
        MMA(o[2 * np],     ph[kc], vh4[0], vh4[1]);
        MMA(o[2 * np],     pl[kc], vh4[0], vh4[1]);
        MMA(o[2 * np + 1], ph[kc], vh4[2], vh4[3]);
        MMA(o[2 * np + 1], pl[kc], vh4[2], vh4[3]);
      }
    }
    __syncthreads();
  }

  // epilogue
  const float iA = 1.f / lA, iB = 1.f / lB;
  const long rA = (long)(b * SEQ + q0 + m0 + (lane >> 2));
  const long rB = rA + 8;
#pragma unroll
  for (int nt = 0; nt < 8; nt++) {
    const int col = h * HDIM + nt * 8 + (lane & 3) * 2;
    *(float2*)(g_X + rA * HIDN + col) = make_float2(o[nt][0] * iA, o[nt][1] * iA);
    *(float2*)(g_X + rB * HIDN + col) = make_float2(o[nt][2] * iB, o[nt][3] * iB);
  }
}

// ---------------- launch -----------------------------------------------------
extern "C" void kernel_launch(void* const* d_in, const int* in_sizes, int n_in,
                              void* d_out, int out_size) {
  const float* q   = (const float*)d_in[0];
  const float* k   = (const float*)d_in[1];
  const float* v   = (const float*)d_in[2];
  const float* g1q = (const float*)d_in[3];
  const float* b1q = (const float*)d_in[4];
  const float* g1k = (const float*)d_in[5];
  const float* b1k = (const float*)d_in[6];
  const float* g1v = (const float*)d_in[7];
  const float* b1v = (const float*)d_in[8];
  const float* Wq  = (const float*)d_in[9];
  const float* bq  = (const float*)d_in[10];
  const float* Wk  = (const float*)d_in[11];
  const float* bk  = (const float*)d_in[12];
  const float* Wv  = (const float*)d_in[13];
  const float* bv  = (const float*)d_in[14];
  const float* g2  = (const float*)d_in[15];
  const float* b2  = (const float*)d_in[16];
  const float* g3  = (const float*)d_in[17];
  const float* b3  = (const float*)d_in[18];
  const float* Wf  = (const float*)d_in[19];
  const float* bf  = (const float*)d_in[20];
  const int*  mask = (const int*)d_in[21];
  float* out = (float*)d_out;

  cudaFuncSetAttribute(gemm_mma, cudaFuncAttributeMaxDynamicSharedMemorySize, GEMM_SMEM);
  cudaFuncSetAttribute(attn_mma, cudaFuncAttributeMaxDynamicSharedMemorySize, ATTN_SMEM);

  // 0) weight split (hi/lo fp16)
  wconv_kernel<<<dim3(WSZ / 1024, 4), 256>>>(Wq, Wk, Wv, Wf);

  // 1) LayerNorms of q,k,v -> fp16 hi slots 0..2 (one launch)
  ln3_kernel<<<dim3(MROWS, 3), 256>>>(q, g1q, b1q, k, g1k, b1k, v, g1v, b1v);

  // 2) Q/K/V projections (fused z=0..2) -> g_P fp32
  gemm_mma<<<dim3(HIDN / BN, MROWS / BM, 3), 256, GEMM_SMEM>>>(0, 0, 0, bq, bk, bv);

  // 3) RoPE + split: Q hi, K hi+lo, V hi
  rope_split_kernel<<<dim3(MROWS, 3), 512>>>();

  // 4) fp16 tensor-core flash attention -> g_X
  attn_mma<<<dim3(SEQ / 64, NHEAD, 4), 128, ATTN_SMEM>>>(mask);

  // 5) fx = LN(x) -> g_Fx fp32 + slot 3 fp16 hi
  ln_fx_kernel<<<MROWS, 256>>>(g2, b2);

  // 6) fo = relu(fx @ Wf^T + bf)
  gemm_mma<<<dim3(HIDN / BN, MROWS / BM, 1), 256, GEMM_SMEM>>>(3, 1, 1, bf, bf, bf);

  // 7) out = fx + LN(fo)
  ln_add_kernel<<<MROWS, 256>>>(g3, b3, out);
}